// round 5
// baseline (speedup 1.0000x reference)
#include <cuda_runtime.h>
#include <math.h>
#include <stdint.h>

#define HW    4096
#define CIN   512
#define COUT  256
#define BATCH 32

// ---- proj GEMM tiling ----
#define BM 64
#define BN 256
#define BK 16
#define NKT (CIN / BK)          // 32 k-tiles
#define NSTB 4                  // B pipeline stages
#define A_STRIDE 516
#define B_STRIDE 264
#define A_BYTES (BM * A_STRIDE * 4)          // 132096
#define B_STAGE_BYTES (BK * B_STRIDE * 4)    // 16896
#define PBUF_OFF (A_BYTES + NSTB * B_STAGE_BYTES)       // 199680
#define GACC_OFF (PBUF_OFF + 256 * 4)                   // 200704
#define SMEM_TOTAL (GACC_OFF + 512 * 4)                 // 202752

// ---- attn smem layout ----
#define MS_STRIDE 260
#define MT_STRIDE 36
#define LS_STRIDE 136
#define AT_MEMS_OFF 0
#define AT_MEMT_OFF (32 * MS_STRIDE * 4)                 // 33280
#define AT_LSM_OFF  (AT_MEMT_OFF + 256 * MT_STRIDE * 4)  // 70144
#define AT_STG_OFF  (AT_LSM_OFF + 32 * LS_STRIDE * 4)    // 87552
#define AT_STAGE_BYTES (16 * LS_STRIDE * 4)              // 8704
#define AT_SMEM_TOTAL (AT_STG_OFF + 3 * AT_STAGE_BYTES)  // 113664

// ---------------- device scratch ----------------
__device__ float g_part[16][BATCH][CIN];   // per-n-tile partials of feats*preds
__device__ float g_predsum[BATCH];
__device__ float g_pooled[BATCH * COUT];
__device__ float g_mem[BATCH * COUT];
__device__ int   g_ptr;

__device__ __forceinline__ float warp_sum(float v) {
#pragma unroll
    for (int o = 16; o; o >>= 1) v += __shfl_down_sync(0xffffffffu, v, o);
    return v;
}
__device__ __forceinline__ uint32_t smem_u32(const void* p) {
    uint32_t a;
    asm("{ .reg .u64 t; cvta.to.shared.u64 t, %1; cvt.u32.u64 %0, t; }" : "=r"(a) : "l"(p));
    return a;
}
__device__ __forceinline__ uint32_t f2tf32(float f) {
    uint32_t r;
    asm("cvt.rna.tf32.f32 %0, %1;" : "=r"(r) : "f"(f));
    return r;
}
#define CP_ASYNC16(saddr, gaddr) \
    asm volatile("cp.async.cg.shared.global [%0], [%1], 16;" :: "r"(saddr), "l"(gaddr))
#define CP_COMMIT()   asm volatile("cp.async.commit_group;" ::: "memory")
#define CP_WAIT(n)    asm volatile("cp.async.wait_group %0;" :: "n"(n) : "memory")

#define MMA_TF32(c, a, bf) \
    asm volatile("mma.sync.aligned.m16n8k8.row.col.f32.tf32.tf32.f32 " \
        "{%0,%1,%2,%3}, {%4,%5,%6,%7}, {%8,%9}, {%0,%1,%2,%3};" \
        : "+f"((c)[0]), "+f"((c)[1]), "+f"((c)[2]), "+f"((c)[3]) \
        : "r"((a)[0]), "r"((a)[1]), "r"((a)[2]), "r"((a)[3]), \
          "r"((bf)[0]), "r"((bf)[1]))

// ---------------- predsum ----------------
__global__ void predsum_kernel(const float* __restrict__ preds) {
    int b = blockIdx.x;
    const float* pr = preds + (size_t)b * HW;
    int t = threadIdx.x;
    float s = 0.f;
    for (int i = t; i < HW; i += 256) s += pr[i];
    s = warp_sum(s);
    __shared__ float red[8];
    if ((t & 31) == 0) red[t >> 5] = s;
    __syncthreads();
    if (t == 0) {
        float tt = 0.f;
#pragma unroll
        for (int j = 0; j < 8; j++) tt += red[j];
        g_predsum[b] = tt;
    }
}

// ---------------- pooled: reduce g_part, then W @ g ----------------
__global__ void pooled_kernel(const float* __restrict__ W,
                              const float* __restrict__ bias) {
    __shared__ float gs[CIN];
    int b = blockIdx.x;
    int t = threadIdx.x;
    float s0 = 0.f, s1 = 0.f;
#pragma unroll
    for (int si = 0; si < 16; si++) {
        s0 += g_part[si][b][t];
        s1 += g_part[si][b][t + 256];
    }
    gs[t] = s0;
    gs[t + 256] = s1;
    __syncthreads();
    const float* wr = W + (size_t)t * CIN;
    float s = 0.f;
#pragma unroll 8
    for (int c = 0; c < CIN; c++) s += wr[c] * gs[c];
    g_pooled[b * COUT + t] = (s + bias[t] * g_predsum[b]) * (1.0f / (float)HW);
}

// ---------------- memscan: single warp, slot-per-lane ----------------
__global__ void memscan_kernel(const int* __restrict__ epoch_p) {
    __shared__ float px[32 * 260];   // pooled rows (pad 260: 16B-aligned rows)
    __shared__ float ms[32 * 257];   // codebook  (pad 257: conflict-free dot)

    int lane = threadIdx.x;          // 32 threads
    float threshold = ((float)(*epoch_p) / 10.0f - 2.0f) * 0.4f / 13.0f + 0.3f;

    // load pooled (coalesced)
    for (int i4 = lane; i4 < 2048; i4 += 32) {
        int row = i4 >> 6, c4 = (i4 & 63) * 4;
        *(float4*)&px[row * 260 + c4] = *(const float4*)&g_pooled[row * 256 + c4];
    }
    __syncwarp();

    // per-lane: norm of pooled row `lane`
    float nx2 = 0.f;
    for (int c = 0; c < 256; c += 4) {
        float4 v = *(const float4*)&px[lane * 260 + c];
        nx2 += v.x * v.x + v.y * v.y + v.z * v.z + v.w * v.w;
    }
    float rx = rsqrtf(nx2);

    float m2 = 0.f;   // my slot's ||mem||^2
    int ptr = 0;

    for (int i = 0; i < BATCH; i++) {
        // dot(mem[lane], x_i)  -- ms stride 257: (lane + c) % 32 distinct
        float d0 = 0.f, d1 = 0.f, d2 = 0.f, d3 = 0.f;
        if (lane < ptr) {
            const float* mr = &ms[lane * 257];
            const float* xr = &px[i * 260];
#pragma unroll 8
            for (int c = 0; c < 256; c += 4) {
                d0 += mr[c + 0] * xr[c + 0];
                d1 += mr[c + 1] * xr[c + 1];
                d2 += mr[c + 2] * xr[c + 2];
                d3 += mr[c + 3] * xr[c + 3];
            }
        }
        float dot = (d0 + d1) + (d2 + d3);
        float rxi = __shfl_sync(0xffffffffu, rx, i);
        float rm  = (m2 == 0.f) ? 1.0f : rsqrtf(m2);
        float sim = (lane < ptr) ? dot * rm * rxi : -INFINITY;

        // warp argmax, first-index tie-break
        float bv = sim; int bi = lane;
#pragma unroll
        for (int o = 16; o; o >>= 1) {
            float ov = __shfl_xor_sync(0xffffffffu, bv, o);
            int   oi = __shfl_xor_sync(0xffffffffu, bi, o);
            if (ov > bv || (ov == bv && oi < bi)) { bv = ov; bi = oi; }
        }
        int ema = (ptr > 0) && (bv >= threshold);
        int idx = ema ? bi : ptr;

        // update row idx (lane owns 8 cols), track new norm^2
        float ns2 = 0.f;
#pragma unroll
        for (int j = 0; j < 8; j++) {
            int c = lane * 8 + j;
            float xv = px[i * 260 + c];
            float nv = ema ? (ms[idx * 257 + c] * 0.9f + 0.1f * xv) : xv;
            ms[idx * 257 + c] = nv;
            ns2 += nv * nv;
        }
#pragma unroll
        for (int o = 16; o; o >>= 1) ns2 += __shfl_xor_sync(0xffffffffu, ns2, o);
        if (lane == idx) m2 = ns2;
        if (!ema) ptr++;
        __syncwarp();
    }

    for (int idx = lane; idx < ptr * 256; idx += 32)
        g_mem[idx] = ms[(idx >> 8) * 257 + (idx & 255)];
    if (lane == 0) g_ptr = ptr;
}

// ---------------- proj GEMM (tf32 mma) + fused g partials ----------------
__global__ __launch_bounds__(256, 1)
void proj_mma(const float* __restrict__ feats,
              const float* __restrict__ preds,
              const float* __restrict__ W,
              const float* __restrict__ bias,
              float* __restrict__ out) {
    extern __shared__ char smem[];
    float* As   = (float*)smem;
    float* Bs   = (float*)(smem + A_BYTES);
    float* pbuf = (float*)(smem + PBUF_OFF);
    float* gacc = (float*)(smem + GACC_OFF);

    int t = threadIdx.x, wid = t >> 5, lane = t & 31;
    int g = lane >> 2, tg = lane & 3;
    int b  = blockIdx.z;
    int m0 = blockIdx.y * BM;
    int n0 = blockIdx.x * BN;
    int warp_m = (wid >> 2) * 32;
    int warp_n = (wid & 3) * 64;
    bool do_g = (blockIdx.y == 0);

    const float* fb = feats + (size_t)b * CIN * HW + n0;
    uint32_t sB = smem_u32(Bs);

    if (do_g) pbuf[t] = preds[(size_t)b * HW + n0 + t];

    // stage A slice (64 x 512) as tf32
#pragma unroll
    for (int i = 0; i < 32; i++) {
        int c = t + i * 256;
        int row = c >> 7, col4 = (c & 127) * 4;
        float4 v = *(const float4*)(W + (size_t)(m0 + row) * CIN + col4);
        uint4 u;
        u.x = f2tf32(v.x); u.y = f2tf32(v.y);
        u.z = f2tf32(v.z); u.w = f2tf32(v.w);
        *(uint4*)(As + row * A_STRIDE + col4) = u;
    }

#pragma unroll
    for (int s = 0; s < NSTB - 1; s++) {
#pragma unroll
        for (int i = 0; i < 4; i++) {
            int c = t + i * 256;
            int row = c >> 6, col16 = c & 63;
            CP_ASYNC16(sB + s * B_STAGE_BYTES + row * (B_STRIDE * 4) + col16 * 16,
                       fb + (size_t)(s * BK + row) * HW + col16 * 4);
        }
        CP_COMMIT();
    }
    __syncthreads();

    float acc[2][8][4];
#pragma unroll
    for (int mt = 0; mt < 2; mt++)
#pragma unroll
        for (int nt = 0; nt < 8; nt++)
#pragma unroll
            for (int q = 0; q < 4; q++) acc[mt][nt][q] = 0.f;

    for (int kt = 0; kt < NKT; kt++) {
        if (kt + NSTB - 1 < NKT) {
            int s = (kt + NSTB - 1) & (NSTB - 1);
#pragma unroll
            for (int i = 0; i < 4; i++) {
                int c = t + i * 256;
                int row = c >> 6, col16 = c & 63;
                CP_ASYNC16(sB + s * B_STAGE_BYTES + row * (B_STRIDE * 4) + col16 * 16,
                           fb + (size_t)((kt + NSTB - 1) * BK + row) * HW + col16 * 4);
            }
        }
        CP_COMMIT();
        CP_WAIT(2);
        __syncthreads();

        const float* BsS = Bs + (kt & (NSTB - 1)) * (BK * B_STRIDE);

        // fused g partial: g[b, kt*16+kk] += sum_n feats*preds (blockIdx.y==0 only)
        if (do_g) {
            int kk = t >> 4, seg = t & 15;
            float s = 0.f;
#pragma unroll
            for (int j = 0; j < 16; j++)
                s += BsS[kk * B_STRIDE + seg + 16 * j] * pbuf[seg + 16 * j];
#pragma unroll
            for (int o = 8; o; o >>= 1) s += __shfl_down_sync(0xffffffffu, s, o, 16);
            if (seg == 0) gacc[kt * 16 + kk] = s;
        }

#pragma unroll
        for (int kk = 0; kk < 2; kk++) {
            uint32_t af[2][4];
#pragma unroll
            for (int mt = 0; mt < 2; mt++) {
                const float* ap = As + (size_t)(warp_m + mt * 16 + g) * A_STRIDE
                                  + kt * BK + kk * 8 + tg;
                af[mt][0] = __float_as_uint(ap[0]);
                af[mt][1] = __float_as_uint(ap[8 * A_STRIDE]);
                af[mt][2] = __float_as_uint(ap[4]);
                af[mt][3] = __float_as_uint(ap[8 * A_STRIDE + 4]);
            }
            uint32_t bf[8][2];
#pragma unroll
            for (int nt = 0; nt < 8; nt++) {
                const float* bp = BsS + (kk * 8 + tg) * B_STRIDE + warp_n + nt * 8 + g;
                bf[nt][0] = f2tf32(bp[0]);
                bf[nt][1] = f2tf32(bp[4 * B_STRIDE]);
            }
#pragma unroll
            for (int mt = 0; mt < 2; mt++)
#pragma unroll
                for (int nt = 0; nt < 8; nt++)
                    MMA_TF32(acc[mt][nt], af[mt], bf[nt]);
        }
        __syncthreads();
    }

    if (do_g) {
        g_part[blockIdx.x][b][t]       = gacc[t];
        g_part[blockIdx.x][b][t + 256] = gacc[t + 256];
    }

#pragma unroll
    for (int mt = 0; mt < 2; mt++) {
        int m = m0 + warp_m + mt * 16 + g;
        float bv0 = bias[m], bv1 = bias[m + 8];
        float* rowp = out + ((size_t)b * (2 * COUT) + m) * HW + n0 + warp_n + 2 * tg;
#pragma unroll
        for (int nt = 0; nt < 8; nt++) {
            *(float2*)(rowp + nt * 8)          = make_float2(acc[mt][nt][0] + bv0, acc[mt][nt][1] + bv0);
            *(float2*)(rowp + nt * 8 + 8 * HW) = make_float2(acc[mt][nt][2] + bv1, acc[mt][nt][3] + bv1);
        }
    }
}

// ---------------- attention via tf32 mma ----------------
__global__ __launch_bounds__(256, 1)
void attn_mma(float* __restrict__ out) {
    extern __shared__ char smc[];
    float* memS = (float*)(smc + AT_MEMS_OFF);   // [32][260]  A for logit
    float* memT = (float*)(smc + AT_MEMT_OFF);   // [256][36]  A for aug
    float* lsm  = (float*)(smc + AT_LSM_OFF);    // [32][136]  logits/attn
    float* stg  = (float*)(smc + AT_STG_OFF);    // 3 x [16][136] proj stages

    int t = threadIdx.x, wid = t >> 5, lane = t & 31;
    int g = lane >> 2, tg = lane & 3;
    int b = blockIdx.y, l0 = blockIdx.x * 128;
    int ptr = g_ptr;

    for (int idx = t; idx < 32 * 256; idx += 256) {
        int p = idx >> 8, c = idx & 255;
        memS[p * MS_STRIDE + c] = (p < ptr) ? g_mem[idx] : 0.f;
    }
    __syncthreads();
    for (int p = 0; p < 32; p++)
        memT[t * MT_STRIDE + p] = memS[p * MS_STRIDE + t];

    const float* proj = out + (size_t)b * (2 * COUT) * HW;
    float* aug = out + (size_t)b * (2 * COUT) * HW + (size_t)COUT * HW + l0;
    uint32_t sStg = smem_u32(stg);

#pragma unroll
    for (int s = 0; s < 2; s++) {
        if (t < 128) {
            int r = t >> 3, c16 = t & 7;
            CP_ASYNC16(sStg + s * AT_STAGE_BYTES + r * (LS_STRIDE * 4) + c16 * 16,
                       proj + (size_t)(s * 16 + r) * HW + l0 + c16 * 4);
        }
        CP_COMMIT();
    }

    // ---- phase 1: logit[p][l] = mem @ proj ----
    float accl[2][2][4];
#pragma unroll
    for (int mt = 0; mt < 2; mt++)
#pragma unroll
        for (int nt = 0; nt < 2; nt++)
#pragma unroll
            for (int q = 0; q < 4; q++) accl[mt][nt][q] = 0.f;
    int n0w = wid * 16;

    for (int kt = 0; kt < 16; kt++) {
        if (kt + 2 < 16) {
            int s = (kt + 2) % 3;
            if (t < 128) {
                int r = t >> 3, c16 = t & 7;
                CP_ASYNC16(sStg + s * AT_STAGE_BYTES + r * (LS_STRIDE * 4) + c16 * 16,
                           proj + (size_t)((kt + 2) * 16 + r) * HW + l0 + c16 * 4);
            }
        }
        CP_COMMIT();
        CP_WAIT(2);
        __syncthreads();
        const float* BsS = stg + (kt % 3) * (16 * LS_STRIDE);
#pragma unroll
        for (int kk = 0; kk < 2; kk++) {
            int kc = kt * 16 + kk * 8;
            uint32_t af[2][4];
#pragma unroll
            for (int mt = 0; mt < 2; mt++) {
                const float* ap = memS + (mt * 16 + g) * MS_STRIDE + kc + tg;
                af[mt][0] = f2tf32(ap[0]);
                af[mt][1] = f2tf32(ap[8 * MS_STRIDE]);
                af[mt][2] = f2tf32(ap[4]);
                af[mt][3] = f2tf32(ap[8 * MS_STRIDE + 4]);
            }
            uint32_t bf[2][2];
#pragma unroll
            for (int nt = 0; nt < 2; nt++) {
                const float* bp = BsS + (kk * 8 + tg) * LS_STRIDE + n0w + nt * 8 + g;
                bf[nt][0] = f2tf32(bp[0]);
                bf[nt][1] = f2tf32(bp[4 * LS_STRIDE]);
            }
#pragma unroll
            for (int mt = 0; mt < 2; mt++)
#pragma unroll
                for (int nt = 0; nt < 2; nt++)
                    MMA_TF32(accl[mt][nt], af[mt], bf[nt]);
        }
        __syncthreads();
    }
#pragma unroll
    for (int mt = 0; mt < 2; mt++)
#pragma unroll
        for (int nt = 0; nt < 2; nt++) {
            int p = mt * 16 + g;
            int l = n0w + nt * 8 + 2 * tg;
            *(float2*)&lsm[p * LS_STRIDE + l]       = make_float2(accl[mt][nt][0], accl[mt][nt][1]);
            *(float2*)&lsm[(p + 8) * LS_STRIDE + l] = make_float2(accl[mt][nt][2], accl[mt][nt][3]);
        }
    __syncthreads();

    // ---- phase 2: softmax over valid slots; zero invalid rows ----
    if (t < 128) {
        float mx = -INFINITY;
        for (int p = 0; p < ptr; p++) mx = fmaxf(mx, lsm[p * LS_STRIDE + t]);
        float ss = 0.f;
        for (int p = 0; p < ptr; p++) {
            float e = expf(lsm[p * LS_STRIDE + t] - mx);
            lsm[p * LS_STRIDE + t] = e;
            ss += e;
        }
        float inv = 1.0f / ss;
        for (int p = 0; p < ptr; p++) lsm[p * LS_STRIDE + t] *= inv;
        for (int p = ptr; p < 32; p++) lsm[p * LS_STRIDE + t] = 0.f;
    }
    __syncthreads();

    // ---- phase 3: aug[c][l] = memT @ attn ----
    int m0w = wid * 32;
#pragma unroll
    for (int nh = 0; nh < 2; nh++) {
        float acca[2][8][4];
#pragma unroll
        for (int mt = 0; mt < 2; mt++)
#pragma unroll
            for (int nt = 0; nt < 8; nt++)
#pragma unroll
                for (int q = 0; q < 4; q++) acca[mt][nt][q] = 0.f;
#pragma unroll
        for (int ks = 0; ks < 4; ks++) {
            uint32_t af[2][4];
#pragma unroll
            for (int mt = 0; mt < 2; mt++) {
                const float* ap = memT + (m0w + mt * 16 + g) * MT_STRIDE + ks * 8 + tg;
                af[mt][0] = f2tf32(ap[0]);
                af[mt][1] = f2tf32(ap[8 * MT_STRIDE]);
                af[mt][2] = f2tf32(ap[4]);
                af[mt][3] = f2tf32(ap[8 * MT_STRIDE + 4]);
            }
            uint32_t bf[8][2];
#pragma unroll
            for (int nt = 0; nt < 8; nt++) {
                const float* bp = lsm + (ks * 8 + tg) * LS_STRIDE + nh * 64 + nt * 8 + g;
                bf[nt][0] = f2tf32(bp[0]);
                bf[nt][1] = f2tf32(bp[4 * LS_STRIDE]);
            }
#pragma unroll
            for (int mt = 0; mt < 2; mt++)
#pragma unroll
                for (int nt = 0; nt < 8; nt++)
                    MMA_TF32(acca[mt][nt], af[mt], bf[nt]);
        }
#pragma unroll
        for (int mt = 0; mt < 2; mt++) {
            int c = m0w + mt * 16 + g;
            float* r0 = aug + (size_t)c * HW + nh * 64 + 2 * tg;
            float* r1 = r0 + (size_t)8 * HW;
#pragma unroll
            for (int nt = 0; nt < 8; nt++) {
                *(float2*)(r0 + nt * 8) = make_float2(acca[mt][nt][0], acca[mt][nt][1]);
                *(float2*)(r1 + nt * 8) = make_float2(acca[mt][nt][2], acca[mt][nt][3]);
            }
        }
    }
}

// ---------------- launch --------------------------------------------------
extern "C" void kernel_launch(void* const* d_in, const int* in_sizes, int n_in,
                              void* d_out, int out_size) {
    const float* feats = (const float*)d_in[0];
    const float* preds = (const float*)d_in[1];
    const float* W     = (const float*)d_in[2];
    const float* bias  = (const float*)d_in[3];
    const int*   epoch = (const int*)d_in[4];
    float* out = (float*)d_out;

    cudaFuncSetAttribute(proj_mma, cudaFuncAttributeMaxDynamicSharedMemorySize, SMEM_TOTAL);
    cudaFuncSetAttribute(attn_mma, cudaFuncAttributeMaxDynamicSharedMemorySize, AT_SMEM_TOTAL);

    predsum_kernel<<<BATCH, 256>>>(preds);
    proj_mma<<<dim3(HW / BN, COUT / BM, BATCH), 256, SMEM_TOTAL>>>(feats, preds, W, bias, out);
    pooled_kernel<<<BATCH, 256>>>(W, bias);
    memscan_kernel<<<1, 32>>>(epoch);
    attn_mma<<<dim3(HW / 128, BATCH), 256, AT_SMEM_TOTAL>>>(out);
}

// round 6
// speedup vs baseline: 1.6991x; 1.6991x over previous
#include <cuda_runtime.h>
#include <math.h>
#include <stdint.h>

#define HW    4096
#define CIN   512
#define COUT  256
#define BATCH 32

// ---- proj GEMM tiling (R4, known-good) ----
#define BM 64
#define BN 256
#define BK 16
#define NKT (CIN / BK)
#define NSTB 4
#define A_STRIDE 516
#define B_STRIDE 264
#define A_BYTES (BM * A_STRIDE * 4)
#define B_STAGE_BYTES (BK * B_STRIDE * 4)
#define SMEM_TOTAL (A_BYTES + NSTB * B_STAGE_BYTES)  // 199680

// ---- attn smem layout ----
#define MS_STRIDE 260
#define MT_STRIDE 36
#define LS_STRIDE 136
#define AT_MEMS_OFF 0
#define AT_MEMT_OFF (32 * MS_STRIDE * 4)                 // 33280
#define AT_LSM_OFF  (AT_MEMT_OFF + 256 * MT_STRIDE * 4)  // 70144
#define AT_STG_OFF  (AT_LSM_OFF + 32 * LS_STRIDE * 4)    // 87552
#define AT_STAGE_BYTES (16 * LS_STRIDE * 4)              // 8704
#define AT_SMEM_TOTAL (AT_STG_OFF + 3 * AT_STAGE_BYTES)  // 113664

// ---------------- device scratch ----------------
__device__ float g_g[BATCH * CIN];
__device__ float g_predsum[BATCH];
__device__ float g_pooled[BATCH * COUT];
__device__ float g_mem[BATCH * COUT];
__device__ int   g_ptr;

__device__ __forceinline__ float warp_sum(float v) {
#pragma unroll
    for (int o = 16; o; o >>= 1) v += __shfl_down_sync(0xffffffffu, v, o);
    return v;
}
__device__ __forceinline__ uint32_t smem_u32(const void* p) {
    uint32_t a;
    asm("{ .reg .u64 t; cvta.to.shared.u64 t, %1; cvt.u32.u64 %0, t; }" : "=r"(a) : "l"(p));
    return a;
}
__device__ __forceinline__ uint32_t f2tf32(float f) {
    uint32_t r;
    asm("cvt.rna.tf32.f32 %0, %1;" : "=r"(r) : "f"(f));
    return r;
}
#define CP_ASYNC16(saddr, gaddr) \
    asm volatile("cp.async.cg.shared.global [%0], [%1], 16;" :: "r"(saddr), "l"(gaddr))
#define CP_COMMIT()   asm volatile("cp.async.commit_group;" ::: "memory")
#define CP_WAIT(n)    asm volatile("cp.async.wait_group %0;" :: "n"(n) : "memory")

#define MMA_TF32(c, a, bf) \
    asm volatile("mma.sync.aligned.m16n8k8.row.col.f32.tf32.tf32.f32 " \
        "{%0,%1,%2,%3}, {%4,%5,%6,%7}, {%8,%9}, {%0,%1,%2,%3};" \
        : "+f"((c)[0]), "+f"((c)[1]), "+f"((c)[2]), "+f"((c)[3]) \
        : "r"((a)[0]), "r"((a)[1]), "r"((a)[2]), "r"((a)[3]), \
          "r"((bf)[0]), "r"((bf)[1]))

// ---------------- Kernel A: g[b,c] = sum_hw feats*preds ----
__global__ void gk_kernel(const float* __restrict__ feats,
                          const float* __restrict__ preds) {
    int c = blockIdx.x, b = blockIdx.y;
    const float* f  = feats + ((size_t)b * CIN + c) * HW;
    const float* pr = preds + (size_t)b * HW;
    int t = threadIdx.x;
    float s = 0.f;
#pragma unroll
    for (int i = t * 4; i < HW; i += 1024) {
        float4 fv = *(const float4*)(f + i);
        float4 pv = *(const float4*)(pr + i);
        s += fv.x * pv.x + fv.y * pv.y + fv.z * pv.z + fv.w * pv.w;
    }
    s = warp_sum(s);
    __shared__ float red[8];
    if ((t & 31) == 0) red[t >> 5] = s;
    __syncthreads();
    if (t == 0) {
        float tt = 0.f;
#pragma unroll
        for (int j = 0; j < 8; j++) tt += red[j];
        g_g[b * CIN + c] = tt;
    }
}

__global__ void predsum_kernel(const float* __restrict__ preds) {
    int b = blockIdx.x;
    const float* pr = preds + (size_t)b * HW;
    int t = threadIdx.x;
    float s = 0.f;
    for (int i = t; i < HW; i += 256) s += pr[i];
    s = warp_sum(s);
    __shared__ float red[8];
    if ((t & 31) == 0) red[t >> 5] = s;
    __syncthreads();
    if (t == 0) {
        float tt = 0.f;
#pragma unroll
        for (int j = 0; j < 8; j++) tt += red[j];
        g_predsum[b] = tt;
    }
}

__global__ void pooled_kernel(const float* __restrict__ W,
                              const float* __restrict__ bias) {
    __shared__ float gs[CIN];
    int b = blockIdx.x;
    int t = threadIdx.x;
    gs[t]       = g_g[b * CIN + t];
    gs[t + 256] = g_g[b * CIN + 256 + t];
    __syncthreads();
    const float* wr = W + (size_t)t * CIN;
    float s = 0.f;
#pragma unroll 8
    for (int c = 0; c < CIN; c++) s += wr[c] * gs[c];
    g_pooled[b * COUT + t] = (s + bias[t] * g_predsum[b]) * (1.0f / (float)HW);
}

// ---------------- memscan v3: 32 warps, warp-per-slot ----------------
__global__ void memscan_kernel(const int* __restrict__ epoch_p) {
    __shared__ float px[32 * 264];   // pooled rows, stride 264 (lane-strided conflict-free)
    __shared__ float ms[32 * 264];   // codebook
    __shared__ float rxs[32];        // rsqrt(||x_i||^2)
    __shared__ float m2s[32];        // ||mem[p]||^2
    __shared__ float sims[32];
    __shared__ int   s_ptr, s_idx, s_ema;

    int t = threadIdx.x, w = t >> 5, lane = t & 31;
    float threshold = ((float)(*epoch_p) / 10.0f - 2.0f) * 0.4f / 13.0f + 0.3f;

    // load pooled rows (coalesced float4)
    for (int i = t; i < 2048; i += 1024) {
        int row = i >> 6, c4 = (i & 63) * 4;
        *(float4*)&px[row * 264 + c4] = *(const float4*)&g_pooled[row * 256 + c4];
    }
    if (t == 0) s_ptr = 0;
    __syncthreads();

    // warp w: rsqrt norm of pooled row w
    {
        float s = 0.f;
#pragma unroll
        for (int j = 0; j < 8; j++) {
            float v = px[w * 264 + lane + 32 * j];
            s += v * v;
        }
        s = warp_sum(s);
        if (lane == 0) rxs[w] = rsqrtf(s);
    }
    __syncthreads();

    for (int i = 0; i < BATCH; i++) {
        int ptr = s_ptr;
        // warp w: cosine sim of slot w vs x_i
        float d = 0.f;
        if (w < ptr) {
#pragma unroll
            for (int j = 0; j < 8; j++)
                d += ms[w * 264 + lane + 32 * j] * px[i * 264 + lane + 32 * j];
        }
        d = warp_sum(d);
        if (lane == 0) {
            if (w < ptr) {
                float m2 = m2s[w];
                float rm = (m2 == 0.f) ? 1.0f : rsqrtf(m2);
                sims[w] = d * rm * rxs[i];
            } else {
                sims[w] = -INFINITY;
            }
        }
        __syncthreads();
        if (w == 0) {
            float bv = sims[lane];
            int   bi = lane;
#pragma unroll
            for (int o = 16; o; o >>= 1) {
                float ov = __shfl_xor_sync(0xffffffffu, bv, o);
                int   oi = __shfl_xor_sync(0xffffffffu, bi, o);
                if (ov > bv || (ov == bv && oi < bi)) { bv = ov; bi = oi; }
            }
            if (lane == 0) {
                int ema = (ptr > 0) && (bv >= threshold);
                s_ema = ema;
                s_idx = ema ? bi : ptr;
                if (!ema) s_ptr = ptr + 1;
            }
        }
        __syncthreads();
        if (w == 0) {
            int idx = s_idx, ema = s_ema;
            float ns2 = 0.f;
#pragma unroll
            for (int j = 0; j < 8; j++) {
                int c = lane + 32 * j;
                float xv = px[i * 264 + c];
                float nv = ema ? (ms[idx * 264 + c] * 0.9f + 0.1f * xv) : xv;
                ms[idx * 264 + c] = nv;
                ns2 += nv * nv;
            }
            ns2 = warp_sum(ns2);
            if (lane == 0) m2s[idx] = ns2;
        }
        __syncthreads();
    }

    int ptr = s_ptr;
    for (int i = t; i < ptr * 256; i += 1024)
        g_mem[i] = ms[(i >> 8) * 264 + (i & 255)];
    if (t == 0) g_ptr = ptr;
}

// ---------------- proj GEMM (R4 tf32 mma, unchanged) ----------------
__global__ __launch_bounds__(256, 1)
void proj_mma(const float* __restrict__ feats,
              const float* __restrict__ W,
              const float* __restrict__ bias,
              float* __restrict__ out) {
    extern __shared__ char smem[];
    float* As = (float*)smem;
    float* Bs = (float*)(smem + A_BYTES);

    int t = threadIdx.x, wid = t >> 5, lane = t & 31;
    int g = lane >> 2, tg = lane & 3;
    int b  = blockIdx.z;
    int m0 = blockIdx.y * BM;
    int n0 = blockIdx.x * BN;
    int warp_m = (wid >> 2) * 32;
    int warp_n = (wid & 3) * 64;

    const float* fb = feats + (size_t)b * CIN * HW + n0;
    uint32_t sB = smem_u32(Bs);

#pragma unroll
    for (int i = 0; i < 32; i++) {
        int c = t + i * 256;
        int row = c >> 7, col4 = (c & 127) * 4;
        float4 v = *(const float4*)(W + (size_t)(m0 + row) * CIN + col4);
        uint4 u;
        u.x = f2tf32(v.x); u.y = f2tf32(v.y);
        u.z = f2tf32(v.z); u.w = f2tf32(v.w);
        *(uint4*)(As + row * A_STRIDE + col4) = u;
    }

#pragma unroll
    for (int s = 0; s < NSTB - 1; s++) {
#pragma unroll
        for (int i = 0; i < 4; i++) {
            int c = t + i * 256;
            int row = c >> 6, col16 = c & 63;
            CP_ASYNC16(sB + s * B_STAGE_BYTES + row * (B_STRIDE * 4) + col16 * 16,
                       fb + (size_t)(s * BK + row) * HW + col16 * 4);
        }
        CP_COMMIT();
    }
    __syncthreads();

    float acc[2][8][4];
#pragma unroll
    for (int mt = 0; mt < 2; mt++)
#pragma unroll
        for (int nt = 0; nt < 8; nt++)
#pragma unroll
            for (int q = 0; q < 4; q++) acc[mt][nt][q] = 0.f;

    for (int kt = 0; kt < NKT; kt++) {
        if (kt + NSTB - 1 < NKT) {
            int s = (kt + NSTB - 1) & (NSTB - 1);
#pragma unroll
            for (int i = 0; i < 4; i++) {
                int c = t + i * 256;
                int row = c >> 6, col16 = c & 63;
                CP_ASYNC16(sB + s * B_STAGE_BYTES + row * (B_STRIDE * 4) + col16 * 16,
                           fb + (size_t)((kt + NSTB - 1) * BK + row) * HW + col16 * 4);
            }
        }
        CP_COMMIT();
        CP_WAIT(2);
        __syncthreads();

        const float* BsS = Bs + (kt & (NSTB - 1)) * (BK * B_STRIDE);
#pragma unroll
        for (int kk = 0; kk < 2; kk++) {
            uint32_t af[2][4];
#pragma unroll
            for (int mt = 0; mt < 2; mt++) {
                const float* ap = As + (size_t)(warp_m + mt * 16 + g) * A_STRIDE
                                  + kt * BK + kk * 8 + tg;
                af[mt][0] = __float_as_uint(ap[0]);
                af[mt][1] = __float_as_uint(ap[8 * A_STRIDE]);
                af[mt][2] = __float_as_uint(ap[4]);
                af[mt][3] = __float_as_uint(ap[8 * A_STRIDE + 4]);
            }
            uint32_t bf[8][2];
#pragma unroll
            for (int nt = 0; nt < 8; nt++) {
                const float* bp = BsS + (kk * 8 + tg) * B_STRIDE + warp_n + nt * 8 + g;
                bf[nt][0] = f2tf32(bp[0]);
                bf[nt][1] = f2tf32(bp[4 * B_STRIDE]);
            }
#pragma unroll
            for (int mt = 0; mt < 2; mt++)
#pragma unroll
                for (int nt = 0; nt < 8; nt++)
                    MMA_TF32(acc[mt][nt], af[mt], bf[nt]);
        }
        __syncthreads();
    }

#pragma unroll
    for (int mt = 0; mt < 2; mt++) {
        int m = m0 + warp_m + mt * 16 + g;
        float bv0 = bias[m], bv1 = bias[m + 8];
        float* rowp = out + ((size_t)b * (2 * COUT) + m) * HW + n0 + warp_n + 2 * tg;
#pragma unroll
        for (int nt = 0; nt < 8; nt++) {
            *(float2*)(rowp + nt * 8)          = make_float2(acc[mt][nt][0] + bv0, acc[mt][nt][1] + bv0);
            *(float2*)(rowp + nt * 8 + 8 * HW) = make_float2(acc[mt][nt][2] + bv1, acc[mt][nt][3] + bv1);
        }
    }
}

// ---------------- attention via tf32 mma (v2: full loads, 2 CTAs/SM) -----
__global__ __launch_bounds__(256, 2)
void attn_mma(float* __restrict__ out) {
    extern __shared__ char smc[];
    float* memS = (float*)(smc + AT_MEMS_OFF);   // [32][260]
    float* memT = (float*)(smc + AT_MEMT_OFF);   // [256][36]
    float* lsm  = (float*)(smc + AT_LSM_OFF);    // [32][136]
    float* stg  = (float*)(smc + AT_STG_OFF);    // 3 x [16][136]

    int t = threadIdx.x, wid = t >> 5, lane = t & 31;
    int g = lane >> 2, tg = lane & 3;
    int b = blockIdx.y, l0 = blockIdx.x * 128;
    int ptr = g_ptr;

    for (int idx = t; idx < 32 * 256; idx += 256) {
        int p = idx >> 8, c = idx & 255;
        memS[p * MS_STRIDE + c] = (p < ptr) ? g_mem[idx] : 0.f;
    }
    __syncthreads();
    for (int p = 0; p < 32; p++)
        memT[t * MT_STRIDE + p] = memS[p * MS_STRIDE + t];

    const float* proj = out + (size_t)b * (2 * COUT) * HW;
    float* aug = out + (size_t)b * (2 * COUT) * HW + (size_t)COUT * HW + l0;
    uint32_t sStg = smem_u32(stg);

    // stage load: FULL tile, 512 x 16B chunks via all 256 threads
#define AT_LOAD(sidx, ktile) do {                                              \
    _Pragma("unroll")                                                          \
    for (int i = 0; i < 2; i++) {                                              \
        int c = t + i * 256;                                                   \
        int r = c >> 5, c16 = c & 31;                                          \
        CP_ASYNC16(sStg + (sidx) * AT_STAGE_BYTES + r * (LS_STRIDE * 4) + c16 * 16, \
                   proj + (size_t)((ktile) * 16 + r) * HW + l0 + c16 * 4);     \
    } } while (0)

    AT_LOAD(0, 0); CP_COMMIT();
    AT_LOAD(1, 1); CP_COMMIT();

    // ---- phase 1: logit[p][l] = mem @ proj ----
    float accl[2][2][4];
#pragma unroll
    for (int mt = 0; mt < 2; mt++)
#pragma unroll
        for (int nt = 0; nt < 2; nt++)
#pragma unroll
            for (int q = 0; q < 4; q++) accl[mt][nt][q] = 0.f;
    int n0w = wid * 16;

    for (int kt = 0; kt < 16; kt++) {
        if (kt + 2 < 16) AT_LOAD((kt + 2) % 3, kt + 2);
        CP_COMMIT();
        CP_WAIT(2);
        __syncthreads();
        const float* BsS = stg + (kt % 3) * (16 * LS_STRIDE);
#pragma unroll
        for (int kk = 0; kk < 2; kk++) {
            int kc = kt * 16 + kk * 8;
            uint32_t af[2][4];
#pragma unroll
            for (int mt = 0; mt < 2; mt++) {
                const float* ap = memS + (mt * 16 + g) * MS_STRIDE + kc + tg;
                af[mt][0] = f2tf32(ap[0]);
                af[mt][1] = f2tf32(ap[8 * MS_STRIDE]);
                af[mt][2] = f2tf32(ap[4]);
                af[mt][3] = f2tf32(ap[8 * MS_STRIDE + 4]);
            }
            uint32_t bf[2][2];
#pragma unroll
            for (int nt = 0; nt < 2; nt++) {
                const float* bp = BsS + (kk * 8 + tg) * LS_STRIDE + n0w + nt * 8 + g;
                bf[nt][0] = f2tf32(bp[0]);
                bf[nt][1] = f2tf32(bp[4 * LS_STRIDE]);
            }
#pragma unroll
            for (int mt = 0; mt < 2; mt++)
#pragma unroll
                for (int nt = 0; nt < 2; nt++)
                    MMA_TF32(accl[mt][nt], af[mt], bf[nt]);
        }
        __syncthreads();
    }
#pragma unroll
    for (int mt = 0; mt < 2; mt++)
#pragma unroll
        for (int nt = 0; nt < 2; nt++) {
            int p = mt * 16 + g;
            int l = n0w + nt * 8 + 2 * tg;
            *(float2*)&lsm[p * LS_STRIDE + l]       = make_float2(accl[mt][nt][0], accl[mt][nt][1]);
            *(float2*)&lsm[(p + 8) * LS_STRIDE + l] = make_float2(accl[mt][nt][2], accl[mt][nt][3]);
        }
    __syncthreads();

    // ---- phase 2: softmax over valid slots; zero invalid rows ----
    if (t < 128) {
        float mx = -INFINITY;
        for (int p = 0; p < ptr; p++) mx = fmaxf(mx, lsm[p * LS_STRIDE + t]);
        float ss = 0.f;
        for (int p = 0; p < ptr; p++) {
            float e = expf(lsm[p * LS_STRIDE + t] - mx);
            lsm[p * LS_STRIDE + t] = e;
            ss += e;
        }
        float inv = 1.0f / ss;
        for (int p = 0; p < ptr; p++) lsm[p * LS_STRIDE + t] *= inv;
        for (int p = ptr; p < 32; p++) lsm[p * LS_STRIDE + t] = 0.f;
    }
    __syncthreads();

    // ---- phase 3: aug[c][l] = memT @ attn ----
    int m0w = wid * 32;
#pragma unroll
    for (int nh = 0; nh < 2; nh++) {
        float acca[2][8][4];
#pragma unroll
        for (int mt = 0; mt < 2; mt++)
#pragma unroll
            for (int nt = 0; nt < 8; nt++)
#pragma unroll
                for (int q = 0; q < 4; q++) acca[mt][nt][q] = 0.f;
#pragma unroll
        for (int ks = 0; ks < 4; ks++) {
            uint32_t af[2][4];
#pragma unroll
            for (int mt = 0; mt < 2; mt++) {
                const float* ap = memT + (m0w + mt * 16 + g) * MT_STRIDE + ks * 8 + tg;
                af[mt][0] = f2tf32(ap[0]);
                af[mt][1] = f2tf32(ap[8 * MT_STRIDE]);
                af[mt][2] = f2tf32(ap[4]);
                af[mt][3] = f2tf32(ap[8 * MT_STRIDE + 4]);
            }
            uint32_t bf[8][2];
#pragma unroll
            for (int nt = 0; nt < 8; nt++) {
                const float* bp = lsm + (ks * 8 + tg) * LS_STRIDE + nh * 64 + nt * 8 + g;
                bf[nt][0] = f2tf32(bp[0]);
                bf[nt][1] = f2tf32(bp[4 * LS_STRIDE]);
            }
#pragma unroll
            for (int mt = 0; mt < 2; mt++)
#pragma unroll
                for (int nt = 0; nt < 8; nt++)
                    MMA_TF32(acca[mt][nt], af[mt], bf[nt]);
        }
#pragma unroll
        for (int mt = 0; mt < 2; mt++) {
            int c = m0w + mt * 16 + g;
            float* r0 = aug + (size_t)c * HW + nh * 64 + 2 * tg;
            float* r1 = r0 + (size_t)8 * HW;
#pragma unroll
            for (int nt = 0; nt < 8; nt++) {
                *(float2*)(r0 + nt * 8) = make_float2(acca[mt][nt][0], acca[mt][nt][1]);
                *(float2*)(r1 + nt * 8) = make_float2(acca[mt][nt][2], acca[mt][nt][3]);
            }
        }
    }
#undef AT_LOAD
}

// ---------------- launch --------------------------------------------------
extern "C" void kernel_launch(void* const* d_in, const int* in_sizes, int n_in,
                              void* d_out, int out_size) {
    const float* feats = (const float*)d_in[0];
    const float* preds = (const float*)d_in[1];
    const float* W     = (const float*)d_in[2];
    const float* bias  = (const float*)d_in[3];
    const int*   epoch = (const int*)d_in[4];
    float* out = (float*)d_out;

    cudaFuncSetAttribute(proj_mma, cudaFuncAttributeMaxDynamicSharedMemorySize, SMEM_TOTAL);
    cudaFuncSetAttribute(attn_mma, cudaFuncAttributeMaxDynamicSharedMemorySize, AT_SMEM_TOTAL);

    gk_kernel<<<dim3(CIN, BATCH), 256>>>(feats, preds);
    predsum_kernel<<<BATCH, 256>>>(preds);
    pooled_kernel<<<BATCH, 256>>>(W, bias);
    memscan_kernel<<<1, 1024>>>(epoch);
    proj_mma<<<dim3(HW / BN, COUT / BM, BATCH), 256, SMEM_TOTAL>>>(feats, W, bias, out);
    attn_mma<<<dim3(HW / 128, BATCH), 256, AT_SMEM_TOTAL>>>(out);
}

// round 7
// speedup vs baseline: 1.7337x; 1.0204x over previous
#include <cuda_runtime.h>
#include <math.h>
#include <stdint.h>

#define HW    4096
#define CIN   512
#define COUT  256
#define BATCH 32

// ---- proj GEMM tiling ----
#define BM 64
#define BN 256
#define BK 16
#define NKT (CIN / BK)
#define NSTB 4
#define A_STRIDE 516
#define B_STRIDE 264
#define A_BYTES (BM * A_STRIDE * 4)          // 132096
#define B_STAGE_BYTES (BK * B_STRIDE * 4)    // 16896
#define PBUF_OFF (A_BYTES + NSTB * B_STAGE_BYTES)   // 199680
#define GACC_OFF (PBUF_OFF + 256 * 4)               // 200704
#define SMEM_TOTAL (GACC_OFF + 512 * 4)             // 202752

// ---- attn smem layout (v3: no memT, 4 stages) ----
#define MS_STRIDE 260
#define LS_STRIDE 136
#define AT_MEMS_OFF 0
#define AT_LSM_OFF  (32 * MS_STRIDE * 4)             // 33280
#define AT_STG_OFF  (AT_LSM_OFF + 32 * LS_STRIDE * 4) // 50688
#define AT_STAGE_BYTES (16 * LS_STRIDE * 4)          // 8704
#define AT_SMEM_TOTAL (AT_STG_OFF + 4 * AT_STAGE_BYTES) // 85504

// ---------------- device scratch ----------------
__device__ float g_part[16][BATCH][CIN];
__device__ float g_predsum[BATCH];
__device__ float g_pooled[BATCH * COUT];
__device__ float g_mem[BATCH * COUT];
__device__ int   g_ptr;

__device__ __forceinline__ float warp_sum(float v) {
#pragma unroll
    for (int o = 16; o; o >>= 1) v += __shfl_down_sync(0xffffffffu, v, o);
    return v;
}
__device__ __forceinline__ uint32_t smem_u32(const void* p) {
    uint32_t a;
    asm("{ .reg .u64 t; cvta.to.shared.u64 t, %1; cvt.u32.u64 %0, t; }" : "=r"(a) : "l"(p));
    return a;
}
__device__ __forceinline__ uint32_t f2tf32(float f) {
    uint32_t r;
    asm("cvt.rna.tf32.f32 %0, %1;" : "=r"(r) : "f"(f));
    return r;
}
#define CP_ASYNC16(saddr, gaddr) \
    asm volatile("cp.async.cg.shared.global [%0], [%1], 16;" :: "r"(saddr), "l"(gaddr))
#define CP_COMMIT()   asm volatile("cp.async.commit_group;" ::: "memory")
#define CP_WAIT(n)    asm volatile("cp.async.wait_group %0;" :: "n"(n) : "memory")

#define MMA_TF32(c, a, bf) \
    asm volatile("mma.sync.aligned.m16n8k8.row.col.f32.tf32.tf32.f32 " \
        "{%0,%1,%2,%3}, {%4,%5,%6,%7}, {%8,%9}, {%0,%1,%2,%3};" \
        : "+f"((c)[0]), "+f"((c)[1]), "+f"((c)[2]), "+f"((c)[3]) \
        : "r"((a)[0]), "r"((a)[1]), "r"((a)[2]), "r"((a)[3]), \
          "r"((bf)[0]), "r"((bf)[1]))

// ---------------- predsum ----------------
__global__ void predsum_kernel(const float* __restrict__ preds) {
    int b = blockIdx.x;
    const float* pr = preds + (size_t)b * HW;
    int t = threadIdx.x;
    float s = 0.f;
    for (int i = t; i < HW; i += 256) s += pr[i];
    s = warp_sum(s);
    __shared__ float red[8];
    if ((t & 31) == 0) red[t >> 5] = s;
    __syncthreads();
    if (t == 0) {
        float tt = 0.f;
#pragma unroll
        for (int j = 0; j < 8; j++) tt += red[j];
        g_predsum[b] = tt;
    }
}

// ---------------- pooled: reduce g_part, then W @ g ----------------
__global__ void pooled_kernel(const float* __restrict__ W,
                              const float* __restrict__ bias) {
    __shared__ float gs[CIN];
    int b = blockIdx.x;
    int t = threadIdx.x;
    float s0 = 0.f, s1 = 0.f;
#pragma unroll
    for (int si = 0; si < 16; si++) {
        s0 += g_part[si][b][t];
        s1 += g_part[si][b][t + 256];
    }
    gs[t] = s0;
    gs[t + 256] = s1;
    __syncthreads();
    const float* wr = W + (size_t)t * CIN;
    float s = 0.f;
#pragma unroll 8
    for (int c = 0; c < CIN; c++) s += wr[c] * gs[c];
    g_pooled[b * COUT + t] = (s + bias[t] * g_predsum[b]) * (1.0f / (float)HW);
}

// ---------------- memscan: 32 warps, warp-per-slot, 2 barriers/iter ------
__global__ void memscan_kernel(const int* __restrict__ epoch_p) {
    __shared__ float px[32 * 264];
    __shared__ float ms[32 * 264];
    __shared__ float rxs[32];
    __shared__ float m2s[32];
    __shared__ float sims[32];
    __shared__ int   s_ptr;

    int t = threadIdx.x, w = t >> 5, lane = t & 31;
    float threshold = ((float)(*epoch_p) / 10.0f - 2.0f) * 0.4f / 13.0f + 0.3f;

    for (int i = t; i < 2048; i += 1024) {
        int row = i >> 6, c4 = (i & 63) * 4;
        *(float4*)&px[row * 264 + c4] = *(const float4*)&g_pooled[row * 256 + c4];
    }
    if (t == 0) s_ptr = 0;
    __syncthreads();

    {   // warp w: rsqrt norm of pooled row w
        float s = 0.f;
#pragma unroll
        for (int j = 0; j < 8; j++) {
            float v = px[w * 264 + lane + 32 * j];
            s += v * v;
        }
        s = warp_sum(s);
        if (lane == 0) rxs[w] = rsqrtf(s);
    }
    __syncthreads();

    for (int i = 0; i < BATCH; i++) {
        int ptr = s_ptr;
        float d = 0.f;
        if (w < ptr) {
#pragma unroll
            for (int j = 0; j < 8; j++)
                d += ms[w * 264 + lane + 32 * j] * px[i * 264 + lane + 32 * j];
        }
        d = warp_sum(d);
        if (lane == 0) {
            if (w < ptr) {
                float m2 = m2s[w];
                float rm = (m2 == 0.f) ? 1.0f : rsqrtf(m2);
                sims[w] = d * rm * rxs[i];
            } else {
                sims[w] = -INFINITY;
            }
        }
        __syncthreads();
        if (w == 0) {
            float bv = sims[lane];
            int   bi = lane;
#pragma unroll
            for (int o = 16; o; o >>= 1) {
                float ov = __shfl_xor_sync(0xffffffffu, bv, o);
                int   oi = __shfl_xor_sync(0xffffffffu, bi, o);
                if (ov > bv || (ov == bv && oi < bi)) { bv = ov; bi = oi; }
            }
            int ema = (ptr > 0) && (bv >= threshold);
            int idx = ema ? bi : ptr;
            float ns2 = 0.f;
#pragma unroll
            for (int j = 0; j < 8; j++) {
                int c = lane + 32 * j;
                float xv = px[i * 264 + c];
                float nv = ema ? (ms[idx * 264 + c] * 0.9f + 0.1f * xv) : xv;
                ms[idx * 264 + c] = nv;
                ns2 += nv * nv;
            }
            ns2 = warp_sum(ns2);
            if (lane == 0) {
                m2s[idx] = ns2;
                if (!ema) s_ptr = ptr + 1;
            }
        }
        __syncthreads();
    }

    int ptr = s_ptr;
    for (int i = t; i < ptr * 256; i += 1024)
        g_mem[i] = ms[(i >> 8) * 264 + (i & 255)];
    if (t == 0) g_ptr = ptr;
}

// ---------------- proj GEMM (tf32 mma) + fused g partials ----------------
__global__ __launch_bounds__(256, 1)
void proj_mma(const float* __restrict__ feats,
              const float* __restrict__ preds,
              const float* __restrict__ W,
              const float* __restrict__ bias,
              float* __restrict__ out) {
    extern __shared__ char smem[];
    float* As   = (float*)smem;
    float* Bs   = (float*)(smem + A_BYTES);
    float* pbuf = (float*)(smem + PBUF_OFF);
    float* gacc = (float*)(smem + GACC_OFF);

    int t = threadIdx.x, wid = t >> 5, lane = t & 31;
    int g = lane >> 2, tg = lane & 3;
    int b  = blockIdx.z;
    int m0 = blockIdx.y * BM;
    int n0 = blockIdx.x * BN;
    int warp_m = (wid >> 2) * 32;
    int warp_n = (wid & 3) * 64;
    bool do_g = (blockIdx.y == 0);

    const float* fb = feats + (size_t)b * CIN * HW + n0;
    uint32_t sB = smem_u32(Bs);

    if (do_g) pbuf[t] = preds[(size_t)b * HW + n0 + t];

#pragma unroll
    for (int i = 0; i < 32; i++) {
        int c = t + i * 256;
        int row = c >> 7, col4 = (c & 127) * 4;
        float4 v = *(const float4*)(W + (size_t)(m0 + row) * CIN + col4);
        uint4 u;
        u.x = f2tf32(v.x); u.y = f2tf32(v.y);
        u.z = f2tf32(v.z); u.w = f2tf32(v.w);
        *(uint4*)(As + row * A_STRIDE + col4) = u;
    }

#pragma unroll
    for (int s = 0; s < NSTB - 1; s++) {
#pragma unroll
        for (int i = 0; i < 4; i++) {
            int c = t + i * 256;
            int row = c >> 6, col16 = c & 63;
            CP_ASYNC16(sB + s * B_STAGE_BYTES + row * (B_STRIDE * 4) + col16 * 16,
                       fb + (size_t)(s * BK + row) * HW + col16 * 4);
        }
        CP_COMMIT();
    }

    float acc[2][8][4];
#pragma unroll
    for (int mt = 0; mt < 2; mt++)
#pragma unroll
        for (int nt = 0; nt < 8; nt++)
#pragma unroll
            for (int q = 0; q < 4; q++) acc[mt][nt][q] = 0.f;

    for (int kt = 0; kt < NKT; kt++) {
        CP_WAIT(2);
        __syncthreads();
        if (kt + NSTB - 1 < NKT) {
            int s = (kt + NSTB - 1) & (NSTB - 1);
#pragma unroll
            for (int i = 0; i < 4; i++) {
                int c = t + i * 256;
                int row = c >> 6, col16 = c & 63;
                CP_ASYNC16(sB + s * B_STAGE_BYTES + row * (B_STRIDE * 4) + col16 * 16,
                           fb + (size_t)((kt + NSTB - 1) * BK + row) * HW + col16 * 4);
            }
        }
        CP_COMMIT();

        const float* BsS = Bs + (kt & (NSTB - 1)) * (BK * B_STRIDE);

        if (do_g) {
            int kk = t >> 4, seg = t & 15;
            float s = 0.f;
#pragma unroll
            for (int j = 0; j < 16; j++)
                s += BsS[kk * B_STRIDE + seg + 16 * j] * pbuf[seg + 16 * j];
#pragma unroll
            for (int o = 8; o; o >>= 1) s += __shfl_down_sync(0xffffffffu, s, o, 16);
            if (seg == 0) gacc[kt * 16 + kk] = s;
        }

#pragma unroll
        for (int kk = 0; kk < 2; kk++) {
            uint32_t af[2][4];
#pragma unroll
            for (int mt = 0; mt < 2; mt++) {
                const float* ap = As + (size_t)(warp_m + mt * 16 + g) * A_STRIDE
                                  + kt * BK + kk * 8 + tg;
                af[mt][0] = __float_as_uint(ap[0]);
                af[mt][1] = __float_as_uint(ap[8 * A_STRIDE]);
                af[mt][2] = __float_as_uint(ap[4]);
                af[mt][3] = __float_as_uint(ap[8 * A_STRIDE + 4]);
            }
            uint32_t bf[8][2];
#pragma unroll
            for (int nt = 0; nt < 8; nt++) {
                const float* bp = BsS + (kk * 8 + tg) * B_STRIDE + warp_n + nt * 8 + g;
                bf[nt][0] = f2tf32(bp[0]);
                bf[nt][1] = f2tf32(bp[4 * B_STRIDE]);
            }
#pragma unroll
            for (int mt = 0; mt < 2; mt++)
#pragma unroll
                for (int nt = 0; nt < 8; nt++)
                    MMA_TF32(acc[mt][nt], af[mt], bf[nt]);
        }
    }
    __syncthreads();

    if (do_g) {
        g_part[blockIdx.x][b][t]       = gacc[t];
        g_part[blockIdx.x][b][t + 256] = gacc[t + 256];
    }

#pragma unroll
    for (int mt = 0; mt < 2; mt++) {
        int m = m0 + warp_m + mt * 16 + g;
        float bv0 = bias[m], bv1 = bias[m + 8];
        float* rowp = out + ((size_t)b * (2 * COUT) + m) * HW + n0 + warp_n + 2 * tg;
#pragma unroll
        for (int nt = 0; nt < 8; nt++) {
            *(float2*)(rowp + nt * 8)          = make_float2(acc[mt][nt][0] + bv0, acc[mt][nt][1] + bv0);
            *(float2*)(rowp + nt * 8 + 8 * HW) = make_float2(acc[mt][nt][2] + bv1, acc[mt][nt][3] + bv1);
        }
    }
}

// ---------------- attention v3: no memT, 4 stages, 1 sync/iter -----------
__global__ __launch_bounds__(256, 2)
void attn_mma(float* __restrict__ out) {
    extern __shared__ char smc[];
    float* memS = (float*)(smc + AT_MEMS_OFF);   // [32][260]
    float* lsm  = (float*)(smc + AT_LSM_OFF);    // [32][136]
    float* stg  = (float*)(smc + AT_STG_OFF);    // 4 x [16][136]

    int t = threadIdx.x, wid = t >> 5, lane = t & 31;
    int g = lane >> 2, tg = lane & 3;
    int b = blockIdx.y, l0 = blockIdx.x * 128;
    int ptr = g_ptr;

    for (int idx = t; idx < 32 * 256; idx += 256) {
        int p = idx >> 8, c = idx & 255;
        memS[p * MS_STRIDE + c] = (p < ptr) ? g_mem[idx] : 0.f;
    }

    const float* proj = out + (size_t)b * (2 * COUT) * HW;
    float* aug = out + (size_t)b * (2 * COUT) * HW + (size_t)COUT * HW + l0;
    uint32_t sStg = smem_u32(stg);

#define AT_LOAD(sidx, ktile) do {                                              \
    _Pragma("unroll")                                                          \
    for (int i = 0; i < 2; i++) {                                              \
        int c = t + i * 256;                                                   \
        int r = c >> 5, c16 = c & 31;                                          \
        CP_ASYNC16(sStg + (sidx) * AT_STAGE_BYTES + r * (LS_STRIDE * 4) + c16 * 16, \
                   proj + (size_t)((ktile) * 16 + r) * HW + l0 + c16 * 4);     \
    } } while (0)

    AT_LOAD(0, 0); CP_COMMIT();
    AT_LOAD(1, 1); CP_COMMIT();
    AT_LOAD(2, 2); CP_COMMIT();

    float accl[2][2][4];
#pragma unroll
    for (int mt = 0; mt < 2; mt++)
#pragma unroll
        for (int nt = 0; nt < 2; nt++)
#pragma unroll
            for (int q = 0; q < 4; q++) accl[mt][nt][q] = 0.f;
    int n0w = wid * 16;

    for (int kt = 0; kt < 16; kt++) {
        CP_WAIT(2);
        __syncthreads();
        if (kt + 3 < 16) AT_LOAD((kt + 3) & 3, kt + 3);
        CP_COMMIT();

        const float* BsS = stg + (kt & 3) * (16 * LS_STRIDE);
#pragma unroll
        for (int kk = 0; kk < 2; kk++) {
            int kc = kt * 16 + kk * 8;
            uint32_t af[2][4];
#pragma unroll
            for (int mt = 0; mt < 2; mt++) {
                const float* ap = memS + (mt * 16 + g) * MS_STRIDE + kc + tg;
                af[mt][0] = f2tf32(ap[0]);
                af[mt][1] = f2tf32(ap[8 * MS_STRIDE]);
                af[mt][2] = f2tf32(ap[4]);
                af[mt][3] = f2tf32(ap[8 * MS_STRIDE + 4]);
            }
            uint32_t bf[2][2];
#pragma unroll
            for (int nt = 0; nt < 2; nt++) {
                const float* bp = BsS + (kk * 8 + tg) * LS_STRIDE + n0w + nt * 8 + g;
                bf[nt][0] = f2tf32(bp[0]);
                bf[nt][1] = f2tf32(bp[4 * LS_STRIDE]);
            }
#pragma unroll
            for (int mt = 0; mt < 2; mt++)
#pragma unroll
                for (int nt = 0; nt < 2; nt++)
                    MMA_TF32(accl[mt][nt], af[mt], bf[nt]);
        }
    }
    __syncthreads();
#pragma unroll
    for (int mt = 0; mt < 2; mt++)
#pragma unroll
        for (int nt = 0; nt < 2; nt++) {
            int p = mt * 16 + g;
            int l = n0w + nt * 8 + 2 * tg;
            *(float2*)&lsm[p * LS_STRIDE + l]       = make_float2(accl[mt][nt][0], accl[mt][nt][1]);
            *(float2*)&lsm[(p + 8) * LS_STRIDE + l] = make_float2(accl[mt][nt][2], accl[mt][nt][3]);
        }
    __syncthreads();

    if (t < 128) {
        float mx = -INFINITY;
        for (int p = 0; p < ptr; p++) mx = fmaxf(mx, lsm[p * LS_STRIDE + t]);
        float ss = 0.f;
        for (int p = 0; p < ptr; p++) {
            float e = expf(lsm[p * LS_STRIDE + t] - mx);
            lsm[p * LS_STRIDE + t] = e;
            ss += e;
        }
        float inv = 1.0f / ss;
        for (int p = 0; p < ptr; p++) lsm[p * LS_STRIDE + t] *= inv;
        for (int p = ptr; p < 32; p++) lsm[p * LS_STRIDE + t] = 0.f;
    }
    __syncthreads();

    // aug[c][l] = sum_p memS[p][c] * attn[p][l]  (A frags read transposed)
    int m0w = wid * 32;
#pragma unroll
    for (int nh = 0; nh < 2; nh++) {
        float acca[2][8][4];
#pragma unroll
        for (int mt = 0; mt < 2; mt++)
#pragma unroll
            for (int nt = 0; nt < 8; nt++)
#pragma unroll
                for (int q = 0; q < 4; q++) acca[mt][nt][q] = 0.f;
#pragma unroll
        for (int ks = 0; ks < 4; ks++) {
            uint32_t af[2][4];
#pragma unroll
            for (int mt = 0; mt < 2; mt++) {
                const float* ap = memS + (ks * 8 + tg) * MS_STRIDE + m0w + mt * 16 + g;
                af[mt][0] = f2tf32(ap[0]);
                af[mt][1] = f2tf32(ap[8]);
                af[mt][2] = f2tf32(ap[4 * MS_STRIDE]);
                af[mt][3] = f2tf32(ap[4 * MS_STRIDE + 8]);
            }
            uint32_t bf[8][2];
#pragma unroll
            for (int nt = 0; nt < 8; nt++) {
                const float* bp = lsm + (ks * 8 + tg) * LS_STRIDE + nh * 64 + nt * 8 + g;
                bf[nt][0] = f2tf32(bp[0]);
                bf[nt][1] = f2tf32(bp[4 * LS_STRIDE]);
            }
#pragma unroll
            for (int mt = 0; mt < 2; mt++)
#pragma unroll
                for (int nt = 0; nt < 8; nt++)
                    MMA_TF32(acca[mt][nt], af[mt], bf[nt]);
        }
#pragma unroll
        for (int mt = 0; mt < 2; mt++) {
            int c = m0w + mt * 16 + g;
            float* r0 = aug + (size_t)c * HW + nh * 64 + 2 * tg;
            float* r1 = r0 + (size_t)8 * HW;
#pragma unroll
            for (int nt = 0; nt < 8; nt++) {
                *(float2*)(r0 + nt * 8) = make_float2(acca[mt][nt][0], acca[mt][nt][1]);
                *(float2*)(r1 + nt * 8) = make_float2(acca[mt][nt][2], acca[mt][nt][3]);
            }
        }
    }
#undef AT_LOAD
}

// ---------------- launch --------------------------------------------------
extern "C" void kernel_launch(void* const* d_in, const int* in_sizes, int n_in,
                              void* d_out, int out_size) {
    const float* feats = (const float*)d_in[0];
    const float* preds = (const float*)d_in[1];
    const float* W     = (const float*)d_in[2];
    const float* bias  = (const float*)d_in[3];
    const int*   epoch = (const int*)d_in[4];
    float* out = (float*)d_out;

    cudaFuncSetAttribute(proj_mma, cudaFuncAttributeMaxDynamicSharedMemorySize, SMEM_TOTAL);
    cudaFuncSetAttribute(attn_mma, cudaFuncAttributeMaxDynamicSharedMemorySize, AT_SMEM_TOTAL);

    predsum_kernel<<<BATCH, 256>>>(preds);
    proj_mma<<<dim3(HW / BN, COUT / BM, BATCH), 256, SMEM_TOTAL>>>(feats, preds, W, bias, out);
    pooled_kernel<<<BATCH, 256>>>(W, bias);
    memscan_kernel<<<1, 1024>>>(epoch);
    attn_mma<<<dim3(HW / 128, BATCH), 256, AT_SMEM_TOTAL>>>(out);
}

// round 8
// speedup vs baseline: 1.8706x; 1.0790x over previous
#include <cuda_runtime.h>
#include <cuda_fp16.h>
#include <math.h>
#include <stdint.h>

#define HW    4096
#define CIN   512
#define COUT  256
#define BATCH 32

// ---- proj GEMM tiling (fp16 MMA) ----
#define BM 64
#define BN 256
#define BK 16
#define NKT (CIN / BK)
#define NSTB 4
#define A_STRIDE_U32 260                      // half2 units per A row
#define B_STRIDE 268                          // fp32 per B stage row (conflict-free for 2tg rows)
#define A_BYTES (BM * A_STRIDE_U32 * 4)       // 66560
#define B_STAGE_BYTES (BK * B_STRIDE * 4)     // 17152
#define PBUF_OFF (A_BYTES + NSTB * B_STAGE_BYTES)   // 135168
#define GACC_OFF (PBUF_OFF + 256 * 4)               // 136192
#define SMEM_TOTAL (GACC_OFF + 512 * 4)             // 138240

// ---- attn smem layout (unchanged R7) ----
#define MS_STRIDE 260
#define LS_STRIDE 136
#define AT_MEMS_OFF 0
#define AT_LSM_OFF  (32 * MS_STRIDE * 4)
#define AT_STG_OFF  (AT_LSM_OFF + 32 * LS_STRIDE * 4)
#define AT_STAGE_BYTES (16 * LS_STRIDE * 4)
#define AT_SMEM_TOTAL (AT_STG_OFF + 4 * AT_STAGE_BYTES) // 85504

// ---------------- device scratch ----------------
__device__ float g_part[16][BATCH][CIN];
__device__ float g_predsum[BATCH];
__device__ float g_pooled[BATCH * COUT];
__device__ float g_mem[BATCH * COUT];
__device__ int   g_ptr;

__device__ __forceinline__ float warp_sum(float v) {
#pragma unroll
    for (int o = 16; o; o >>= 1) v += __shfl_down_sync(0xffffffffu, v, o);
    return v;
}
__device__ __forceinline__ uint32_t smem_u32(const void* p) {
    uint32_t a;
    asm("{ .reg .u64 t; cvta.to.shared.u64 t, %1; cvt.u32.u64 %0, t; }" : "=r"(a) : "l"(p));
    return a;
}
__device__ __forceinline__ uint32_t f2tf32(float f) {
    uint32_t r;
    asm("cvt.rna.tf32.f32 %0, %1;" : "=r"(r) : "f"(f));
    return r;
}
__device__ __forceinline__ uint32_t pack_h2(float lo, float hi) {
    __half2 h = __floats2half2_rn(lo, hi);
    return *(uint32_t*)&h;
}
#define CP_ASYNC16(saddr, gaddr) \
    asm volatile("cp.async.cg.shared.global [%0], [%1], 16;" :: "r"(saddr), "l"(gaddr))
#define CP_COMMIT()   asm volatile("cp.async.commit_group;" ::: "memory")
#define CP_WAIT(n)    asm volatile("cp.async.wait_group %0;" :: "n"(n) : "memory")

#define MMA_TF32(c, a, bf) \
    asm volatile("mma.sync.aligned.m16n8k8.row.col.f32.tf32.tf32.f32 " \
        "{%0,%1,%2,%3}, {%4,%5,%6,%7}, {%8,%9}, {%0,%1,%2,%3};" \
        : "+f"((c)[0]), "+f"((c)[1]), "+f"((c)[2]), "+f"((c)[3]) \
        : "r"((a)[0]), "r"((a)[1]), "r"((a)[2]), "r"((a)[3]), \
          "r"((bf)[0]), "r"((bf)[1]))

#define MMA_F16(c, a, bf) \
    asm volatile("mma.sync.aligned.m16n8k16.row.col.f32.f16.f16.f32 " \
        "{%0,%1,%2,%3}, {%4,%5,%6,%7}, {%8,%9}, {%0,%1,%2,%3};" \
        : "+f"((c)[0]), "+f"((c)[1]), "+f"((c)[2]), "+f"((c)[3]) \
        : "r"((a)[0]), "r"((a)[1]), "r"((a)[2]), "r"((a)[3]), \
          "r"((bf)[0]), "r"((bf)[1]))

// ---------------- predsum ----------------
__global__ void predsum_kernel(const float* __restrict__ preds) {
    int b = blockIdx.x;
    const float* pr = preds + (size_t)b * HW;
    int t = threadIdx.x;
    float s = 0.f;
    for (int i = t; i < HW; i += 256) s += pr[i];
    s = warp_sum(s);
    __shared__ float red[8];
    if ((t & 31) == 0) red[t >> 5] = s;
    __syncthreads();
    if (t == 0) {
        float tt = 0.f;
#pragma unroll
        for (int j = 0; j < 8; j++) tt += red[j];
        g_predsum[b] = tt;
    }
}

// ---------------- pooled ----------------
__global__ void pooled_kernel(const float* __restrict__ W,
                              const float* __restrict__ bias) {
    __shared__ float gs[CIN];
    int b = blockIdx.x;
    int t = threadIdx.x;
    float s0 = 0.f, s1 = 0.f;
#pragma unroll
    for (int si = 0; si < 16; si++) {
        s0 += g_part[si][b][t];
        s1 += g_part[si][b][t + 256];
    }
    gs[t] = s0;
    gs[t + 256] = s1;
    __syncthreads();
    const float* wr = W + (size_t)t * CIN;
    float s = 0.f;
#pragma unroll 8
    for (int c = 0; c < CIN; c++) s += wr[c] * gs[c];
    g_pooled[b * COUT + t] = (s + bias[t] * g_predsum[b]) * (1.0f / (float)HW);
}

// ---------------- memscan (R7, unchanged) ----------------
__global__ void memscan_kernel(const int* __restrict__ epoch_p) {
    __shared__ float px[32 * 264];
    __shared__ float ms[32 * 264];
    __shared__ float rxs[32];
    __shared__ float m2s[32];
    __shared__ float sims[32];
    __shared__ int   s_ptr;

    int t = threadIdx.x, w = t >> 5, lane = t & 31;
    float threshold = ((float)(*epoch_p) / 10.0f - 2.0f) * 0.4f / 13.0f + 0.3f;

    for (int i = t; i < 2048; i += 1024) {
        int row = i >> 6, c4 = (i & 63) * 4;
        *(float4*)&px[row * 264 + c4] = *(const float4*)&g_pooled[row * 256 + c4];
    }
    if (t == 0) s_ptr = 0;
    __syncthreads();

    {
        float s = 0.f;
#pragma unroll
        for (int j = 0; j < 8; j++) {
            float v = px[w * 264 + lane + 32 * j];
            s += v * v;
        }
        s = warp_sum(s);
        if (lane == 0) rxs[w] = rsqrtf(s);
    }
    __syncthreads();

    for (int i = 0; i < BATCH; i++) {
        int ptr = s_ptr;
        float d = 0.f;
        if (w < ptr) {
#pragma unroll
            for (int j = 0; j < 8; j++)
                d += ms[w * 264 + lane + 32 * j] * px[i * 264 + lane + 32 * j];
        }
        d = warp_sum(d);
        if (lane == 0) {
            if (w < ptr) {
                float m2 = m2s[w];
                float rm = (m2 == 0.f) ? 1.0f : rsqrtf(m2);
                sims[w] = d * rm * rxs[i];
            } else {
                sims[w] = -INFINITY;
            }
        }
        __syncthreads();
        if (w == 0) {
            float bv = sims[lane];
            int   bi = lane;
#pragma unroll
            for (int o = 16; o; o >>= 1) {
                float ov = __shfl_xor_sync(0xffffffffu, bv, o);
                int   oi = __shfl_xor_sync(0xffffffffu, bi, o);
                if (ov > bv || (ov == bv && oi < bi)) { bv = ov; bi = oi; }
            }
            int ema = (ptr > 0) && (bv >= threshold);
            int idx = ema ? bi : ptr;
            float ns2 = 0.f;
#pragma unroll
            for (int j = 0; j < 8; j++) {
                int c = lane + 32 * j;
                float xv = px[i * 264 + c];
                float nv = ema ? (ms[idx * 264 + c] * 0.9f + 0.1f * xv) : xv;
                ms[idx * 264 + c] = nv;
                ns2 += nv * nv;
            }
            ns2 = warp_sum(ns2);
            if (lane == 0) {
                m2s[idx] = ns2;
                if (!ema) s_ptr = ptr + 1;
            }
        }
        __syncthreads();
    }

    int ptr = s_ptr;
    for (int i = t; i < ptr * 256; i += 1024)
        g_mem[i] = ms[(i >> 8) * 264 + (i & 255)];
    if (t == 0) g_ptr = ptr;
}

// ---------------- proj GEMM: fp16 m16n8k16 + fused g partials ------------
__global__ __launch_bounds__(256, 1)
void proj_mma(const float* __restrict__ feats,
              const float* __restrict__ preds,
              const float* __restrict__ W,
              const float* __restrict__ bias,
              float* __restrict__ out) {
    extern __shared__ char smem[];
    uint32_t* Au  = (uint32_t*)smem;               // A: [64][260] half2
    float* Bs     = (float*)(smem + A_BYTES);      // 4 stages [16][268] fp32
    float* pbuf   = (float*)(smem + PBUF_OFF);
    float* gacc   = (float*)(smem + GACC_OFF);

    int t = threadIdx.x, wid = t >> 5, lane = t & 31;
    int g = lane >> 2, tg = lane & 3;
    int b  = blockIdx.z;
    int m0 = blockIdx.y * BM;
    int n0 = blockIdx.x * BN;
    int warp_m = (wid >> 2) * 32;
    int warp_n = (wid & 3) * 64;
    bool do_g = (blockIdx.y == 0);

    const float* fb = feats + (size_t)b * CIN * HW + n0;
    uint32_t sB = smem_u32(Bs);

    if (do_g) pbuf[t] = preds[(size_t)b * HW + n0 + t];

    // stage A slice (64 x 512) as packed half2
#pragma unroll
    for (int i = 0; i < 32; i++) {
        int c = t + i * 256;            // float4 id, 8192 total
        int row = c >> 7, col4 = (c & 127) * 4;
        float4 v = *(const float4*)(W + (size_t)(m0 + row) * CIN + col4);
        uint2 u;
        u.x = pack_h2(v.x, v.y);
        u.y = pack_h2(v.z, v.w);
        *(uint2*)(Au + row * A_STRIDE_U32 + (c & 127) * 2) = u;
    }

#pragma unroll
    for (int s = 0; s < NSTB - 1; s++) {
#pragma unroll
        for (int i = 0; i < 4; i++) {
            int c = t + i * 256;
            int row = c >> 6, col16 = c & 63;
            CP_ASYNC16(sB + s * B_STAGE_BYTES + row * (B_STRIDE * 4) + col16 * 16,
                       fb + (size_t)(s * BK + row) * HW + col16 * 4);
        }
        CP_COMMIT();
    }

    float acc[2][8][4];
#pragma unroll
    for (int mt = 0; mt < 2; mt++)
#pragma unroll
        for (int nt = 0; nt < 8; nt++)
#pragma unroll
            for (int q = 0; q < 4; q++) acc[mt][nt][q] = 0.f;

    for (int kt = 0; kt < NKT; kt++) {
        CP_WAIT(2);
        __syncthreads();
        if (kt + NSTB - 1 < NKT) {
            int s = (kt + NSTB - 1) & (NSTB - 1);
#pragma unroll
            for (int i = 0; i < 4; i++) {
                int c = t + i * 256;
                int row = c >> 6, col16 = c & 63;
                CP_ASYNC16(sB + s * B_STAGE_BYTES + row * (B_STRIDE * 4) + col16 * 16,
                           fb + (size_t)((kt + NSTB - 1) * BK + row) * HW + col16 * 4);
            }
        }
        CP_COMMIT();

        const float* BsS = Bs + (kt & (NSTB - 1)) * (BK * B_STRIDE);

        if (do_g) {
            int kk = t >> 4, seg = t & 15;
            float s = 0.f;
#pragma unroll
            for (int j = 0; j < 16; j++)
                s += BsS[kk * B_STRIDE + seg + 16 * j] * pbuf[seg + 16 * j];
#pragma unroll
            for (int o = 8; o; o >>= 1) s += __shfl_down_sync(0xffffffffu, s, o, 16);
            if (seg == 0) gacc[kt * 16 + kk] = s;
        }

        // ---- one fp16 m16n8k16 step covers all 16 k ----
        uint32_t af[2][4];
#pragma unroll
        for (int mt = 0; mt < 2; mt++) {
            const uint32_t* ap = Au + (size_t)(warp_m + mt * 16 + g) * A_STRIDE_U32
                                 + kt * 8 + tg;
            af[mt][0] = ap[0];
            af[mt][1] = ap[8 * A_STRIDE_U32];
            af[mt][2] = ap[4];
            af[mt][3] = ap[8 * A_STRIDE_U32 + 4];
        }
        uint32_t bf[8][2];
        {
            const float* bk0 = BsS + (2 * tg) * B_STRIDE;       // k = 2tg
#pragma unroll
            for (int nt = 0; nt < 8; nt++) {
                int n = warp_n + nt * 8 + g;
                bf[nt][0] = pack_h2(bk0[n],                 bk0[B_STRIDE + n]);
                bf[nt][1] = pack_h2(bk0[8 * B_STRIDE + n],  bk0[9 * B_STRIDE + n]);
            }
        }
#pragma unroll
        for (int mt = 0; mt < 2; mt++)
#pragma unroll
            for (int nt = 0; nt < 8; nt++)
                MMA_F16(acc[mt][nt], af[mt], bf[nt]);
    }
    __syncthreads();

    if (do_g) {
        g_part[blockIdx.x][b][t]       = gacc[t];
        g_part[blockIdx.x][b][t + 256] = gacc[t + 256];
    }

#pragma unroll
    for (int mt = 0; mt < 2; mt++) {
        int m = m0 + warp_m + mt * 16 + g;
        float bv0 = bias[m], bv1 = bias[m + 8];
        float* rowp = out + ((size_t)b * (2 * COUT) + m) * HW + n0 + warp_n + 2 * tg;
#pragma unroll
        for (int nt = 0; nt < 8; nt++) {
            *(float2*)(rowp + nt * 8)          = make_float2(acc[mt][nt][0] + bv0, acc[mt][nt][1] + bv0);
            *(float2*)(rowp + nt * 8 + 8 * HW) = make_float2(acc[mt][nt][2] + bv1, acc[mt][nt][3] + bv1);
        }
    }
}

// ---------------- attention v3 (R7, unchanged) ----------------
__global__ __launch_bounds__(256, 2)
void attn_mma(float* __restrict__ out) {
    extern __shared__ char smc[];
    float* memS = (float*)(smc + AT_MEMS_OFF);
    float* lsm  = (float*)(smc + AT_LSM_OFF);
    float* stg  = (float*)(smc + AT_STG_OFF);

    int t = threadIdx.x, wid = t >> 5, lane = t & 31;
    int g = lane >> 2, tg = lane & 3;
    int b = blockIdx.y, l0 = blockIdx.x * 128;
    int ptr = g_ptr;

    for (int idx = t; idx < 32 * 256; idx += 256) {
        int p = idx >> 8, c = idx & 255;
        memS[p * MS_STRIDE + c] = (p < ptr) ? g_mem[idx] : 0.f;
    }

    const float* proj = out + (size_t)b * (2 * COUT) * HW;
    float* aug = out + (size_t)b * (2 * COUT) * HW + (size_t)COUT * HW + l0;
    uint32_t sStg = smem_u32(stg);

#define AT_LOAD(sidx, ktile) do {                                              \
    _Pragma("unroll")                                                          \
    for (int i = 0; i < 2; i++) {                                              \
        int c = t + i * 256;                                                   \
        int r = c >> 5, c16 = c & 31;                                          \
        CP_ASYNC16(sStg + (sidx) * AT_STAGE_BYTES + r * (LS_STRIDE * 4) + c16 * 16, \
                   proj + (size_t)((ktile) * 16 + r) * HW + l0 + c16 * 4);     \
    } } while (0)

    AT_LOAD(0, 0); CP_COMMIT();
    AT_LOAD(1, 1); CP_COMMIT();
    AT_LOAD(2, 2); CP_COMMIT();

    float accl[2][2][4];
#pragma unroll
    for (int mt = 0; mt < 2; mt++)
#pragma unroll
        for (int nt = 0; nt < 2; nt++)
#pragma unroll
            for (int q = 0; q < 4; q++) accl[mt][nt][q] = 0.f;
    int n0w = wid * 16;

    for (int kt = 0; kt < 16; kt++) {
        CP_WAIT(2);
        __syncthreads();
        if (kt + 3 < 16) AT_LOAD((kt + 3) & 3, kt + 3);
        CP_COMMIT();

        const float* BsS = stg + (kt & 3) * (16 * LS_STRIDE);
#pragma unroll
        for (int kk = 0; kk < 2; kk++) {
            int kc = kt * 16 + kk * 8;
            uint32_t af[2][4];
#pragma unroll
            for (int mt = 0; mt < 2; mt++) {
                const float* ap = memS + (mt * 16 + g) * MS_STRIDE + kc + tg;
                af[mt][0] = f2tf32(ap[0]);
                af[mt][1] = f2tf32(ap[8 * MS_STRIDE]);
                af[mt][2] = f2tf32(ap[4]);
                af[mt][3] = f2tf32(ap[8 * MS_STRIDE + 4]);
            }
            uint32_t bf[2][2];
#pragma unroll
            for (int nt = 0; nt < 2; nt++) {
                const float* bp = BsS + (kk * 8 + tg) * LS_STRIDE + n0w + nt * 8 + g;
                bf[nt][0] = f2tf32(bp[0]);
                bf[nt][1] = f2tf32(bp[4 * LS_STRIDE]);
            }
#pragma unroll
            for (int mt = 0; mt < 2; mt++)
#pragma unroll
                for (int nt = 0; nt < 2; nt++)
                    MMA_TF32(accl[mt][nt], af[mt], bf[nt]);
        }
    }
    __syncthreads();
#pragma unroll
    for (int mt = 0; mt < 2; mt++)
#pragma unroll
        for (int nt = 0; nt < 2; nt++) {
            int p = mt * 16 + g;
            int l = n0w + nt * 8 + 2 * tg;
            *(float2*)&lsm[p * LS_STRIDE + l]       = make_float2(accl[mt][nt][0], accl[mt][nt][1]);
            *(float2*)&lsm[(p + 8) * LS_STRIDE + l] = make_float2(accl[mt][nt][2], accl[mt][nt][3]);
        }
    __syncthreads();

    if (t < 128) {
        float mx = -INFINITY;
        for (int p = 0; p < ptr; p++) mx = fmaxf(mx, lsm[p * LS_STRIDE + t]);
        float ss = 0.f;
        for (int p = 0; p < ptr; p++) {
            float e = expf(lsm[p * LS_STRIDE + t] - mx);
            lsm[p * LS_STRIDE + t] = e;
            ss += e;
        }
        float inv = 1.0f / ss;
        for (int p = 0; p < ptr; p++) lsm[p * LS_STRIDE + t] *= inv;
        for (int p = ptr; p < 32; p++) lsm[p * LS_STRIDE + t] = 0.f;
    }
    __syncthreads();

    int m0w = wid * 32;
#pragma unroll
    for (int nh = 0; nh < 2; nh++) {
        float acca[2][8][4];
#pragma unroll
        for (int mt = 0; mt < 2; mt++)
#pragma unroll
            for (int nt = 0; nt < 8; nt++)
#pragma unroll
                for (int q = 0; q < 4; q++) acca[mt][nt][q] = 0.f;
#pragma unroll
        for (int ks = 0; ks < 4; ks++) {
            uint32_t af[2][4];
#pragma unroll
            for (int mt = 0; mt < 2; mt++) {
                const float* ap = memS + (ks * 8 + tg) * MS_STRIDE + m0w + mt * 16 + g;
                af[mt][0] = f2tf32(ap[0]);
                af[mt][1] = f2tf32(ap[8]);
                af[mt][2] = f2tf32(ap[4 * MS_STRIDE]);
                af[mt][3] = f2tf32(ap[4 * MS_STRIDE + 8]);
            }
            uint32_t bf[8][2];
#pragma unroll
            for (int nt = 0; nt < 8; nt++) {
                const float* bp = lsm + (ks * 8 + tg) * LS_STRIDE + nh * 64 + nt * 8 + g;
                bf[nt][0] = f2tf32(bp[0]);
                bf[nt][1] = f2tf32(bp[4 * LS_STRIDE]);
            }
#pragma unroll
            for (int mt = 0; mt < 2; mt++)
#pragma unroll
                for (int nt = 0; nt < 8; nt++)
                    MMA_TF32(acca[mt][nt], af[mt], bf[nt]);
        }
#pragma unroll
        for (int mt = 0; mt < 2; mt++) {
            int c = m0w + mt * 16 + g;
            float* r0 = aug + (size_t)c * HW + nh * 64 + 2 * tg;
            float* r1 = r0 + (size_t)8 * HW;
#pragma unroll
            for (int nt = 0; nt < 8; nt++) {
                *(float2*)(r0 + nt * 8) = make_float2(acca[mt][nt][0], acca[mt][nt][1]);
                *(float2*)(r1 + nt * 8) = make_float2(acca[mt][nt][2], acca[mt][nt][3]);
            }
        }
    }
#undef AT_LOAD
}

// ---------------- launch --------------------------------------------------
extern "C" void kernel_launch(void* const* d_in, const int* in_sizes, int n_in,
                              void* d_out, int out_size) {
    const float* feats = (const float*)d_in[0];
    const float* preds = (const float*)d_in[1];
    const float* W     = (const float*)d_in[2];
    const float* bias  = (const float*)d_in[3];
    const int*   epoch = (const int*)d_in[4];
    float* out = (float*)d_out;

    cudaFuncSetAttribute(proj_mma, cudaFuncAttributeMaxDynamicSharedMemorySize, SMEM_TOTAL);
    cudaFuncSetAttribute(attn_mma, cudaFuncAttributeMaxDynamicSharedMemorySize, AT_SMEM_TOTAL);

    predsum_kernel<<<BATCH, 256>>>(preds);
    proj_mma<<<dim3(HW / BN, COUT / BM, BATCH), 256, SMEM_TOTAL>>>(feats, preds, W, bias, out);
    pooled_kernel<<<BATCH, 256>>>(W, bias);
    memscan_kernel<<<1, 1024>>>(epoch);
    attn_mma<<<dim3(HW / 128, BATCH), 256, AT_SMEM_TOTAL>>>(out);
}

// round 9
// speedup vs baseline: 2.0593x; 1.1009x over previous
#include <cuda_runtime.h>
#include <cuda_fp16.h>
#include <math.h>
#include <stdint.h>

#define HW    4096
#define CIN   512
#define COUT  256
#define BATCH 32

// ---- proj GEMM tiling (fp16 MMA, BM=128 retile) ----
#define BM 128
#define BN 256
#define BK 16
#define NKT (CIN / BK)
#define NSTB 4
#define NTHREADS 512
#define A_STRIDE_U32 260                      // half2 units per A row
#define B_STRIDE 268                          // fp32 per B stage row
#define A_BYTES (BM * A_STRIDE_U32 * 4)       // 133120
#define B_STAGE_BYTES (BK * B_STRIDE * 4)     // 17152
#define PBUF_OFF (A_BYTES + NSTB * B_STAGE_BYTES)   // 201728
#define GACC_OFF (PBUF_OFF + 256 * 4)               // 202752
#define SMEM_TOTAL (GACC_OFF + 512 * 4)             // 204800

// ---- attn smem layout (unchanged) ----
#define MS_STRIDE 260
#define LS_STRIDE 136
#define AT_MEMS_OFF 0
#define AT_LSM_OFF  (32 * MS_STRIDE * 4)
#define AT_STG_OFF  (AT_LSM_OFF + 32 * LS_STRIDE * 4)
#define AT_STAGE_BYTES (16 * LS_STRIDE * 4)
#define AT_SMEM_TOTAL (AT_STG_OFF + 4 * AT_STAGE_BYTES) // 85504

// ---------------- device scratch ----------------
__device__ float g_part[16][BATCH][CIN];
__device__ float g_predsum[BATCH];
__device__ float g_pooled[BATCH * COUT];
__device__ float g_mem[BATCH * COUT];
__device__ int   g_ptr;

__device__ __forceinline__ float warp_sum(float v) {
#pragma unroll
    for (int o = 16; o; o >>= 1) v += __shfl_down_sync(0xffffffffu, v, o);
    return v;
}
__device__ __forceinline__ uint32_t smem_u32(const void* p) {
    uint32_t a;
    asm("{ .reg .u64 t; cvta.to.shared.u64 t, %1; cvt.u32.u64 %0, t; }" : "=r"(a) : "l"(p));
    return a;
}
__device__ __forceinline__ uint32_t f2tf32(float f) {
    uint32_t r;
    asm("cvt.rna.tf32.f32 %0, %1;" : "=r"(r) : "f"(f));
    return r;
}
__device__ __forceinline__ uint32_t pack_h2(float lo, float hi) {
    __half2 h = __floats2half2_rn(lo, hi);
    return *(uint32_t*)&h;
}
#define CP_ASYNC16(saddr, gaddr) \
    asm volatile("cp.async.cg.shared.global [%0], [%1], 16;" :: "r"(saddr), "l"(gaddr))
#define CP_COMMIT()   asm volatile("cp.async.commit_group;" ::: "memory")
#define CP_WAIT(n)    asm volatile("cp.async.wait_group %0;" :: "n"(n) : "memory")

#define MMA_TF32(c, a, bf) \
    asm volatile("mma.sync.aligned.m16n8k8.row.col.f32.tf32.tf32.f32 " \
        "{%0,%1,%2,%3}, {%4,%5,%6,%7}, {%8,%9}, {%0,%1,%2,%3};" \
        : "+f"((c)[0]), "+f"((c)[1]), "+f"((c)[2]), "+f"((c)[3]) \
        : "r"((a)[0]), "r"((a)[1]), "r"((a)[2]), "r"((a)[3]), \
          "r"((bf)[0]), "r"((bf)[1]))

#define MMA_F16(c, a, bf) \
    asm volatile("mma.sync.aligned.m16n8k16.row.col.f32.f16.f16.f32 " \
        "{%0,%1,%2,%3}, {%4,%5,%6,%7}, {%8,%9}, {%0,%1,%2,%3};" \
        : "+f"((c)[0]), "+f"((c)[1]), "+f"((c)[2]), "+f"((c)[3]) \
        : "r"((a)[0]), "r"((a)[1]), "r"((a)[2]), "r"((a)[3]), \
          "r"((bf)[0]), "r"((bf)[1]))

// ---------------- predsum ----------------
__global__ void predsum_kernel(const float* __restrict__ preds) {
    int b = blockIdx.x;
    const float* pr = preds + (size_t)b * HW;
    int t = threadIdx.x;
    float s = 0.f;
    for (int i = t; i < HW; i += 256) s += pr[i];
    s = warp_sum(s);
    __shared__ float red[8];
    if ((t & 31) == 0) red[t >> 5] = s;
    __syncthreads();
    if (t == 0) {
        float tt = 0.f;
#pragma unroll
        for (int j = 0; j < 8; j++) tt += red[j];
        g_predsum[b] = tt;
    }
}

// ---------------- pooled ----------------
__global__ void pooled_kernel(const float* __restrict__ W,
                              const float* __restrict__ bias) {
    __shared__ float gs[CIN];
    int b = blockIdx.x;
    int t = threadIdx.x;
    float s0 = 0.f, s1 = 0.f;
#pragma unroll
    for (int si = 0; si < 16; si++) {
        s0 += g_part[si][b][t];
        s1 += g_part[si][b][t + 256];
    }
    gs[t] = s0;
    gs[t + 256] = s1;
    __syncthreads();
    const float* wr = W + (size_t)t * CIN;
    float s = 0.f;
#pragma unroll 8
    for (int c = 0; c < CIN; c++) s += wr[c] * gs[c];
    g_pooled[b * COUT + t] = (s + bias[t] * g_predsum[b]) * (1.0f / (float)HW);
}

// ---------------- memscan (unchanged) ----------------
__global__ void memscan_kernel(const int* __restrict__ epoch_p) {
    __shared__ float px[32 * 264];
    __shared__ float ms[32 * 264];
    __shared__ float rxs[32];
    __shared__ float m2s[32];
    __shared__ float sims[32];
    __shared__ int   s_ptr;

    int t = threadIdx.x, w = t >> 5, lane = t & 31;
    float threshold = ((float)(*epoch_p) / 10.0f - 2.0f) * 0.4f / 13.0f + 0.3f;

    for (int i = t; i < 2048; i += 1024) {
        int row = i >> 6, c4 = (i & 63) * 4;
        *(float4*)&px[row * 264 + c4] = *(const float4*)&g_pooled[row * 256 + c4];
    }
    if (t == 0) s_ptr = 0;
    __syncthreads();

    {
        float s = 0.f;
#pragma unroll
        for (int j = 0; j < 8; j++) {
            float v = px[w * 264 + lane + 32 * j];
            s += v * v;
        }
        s = warp_sum(s);
        if (lane == 0) rxs[w] = rsqrtf(s);
    }
    __syncthreads();

    for (int i = 0; i < BATCH; i++) {
        int ptr = s_ptr;
        float d = 0.f;
        if (w < ptr) {
#pragma unroll
            for (int j = 0; j < 8; j++)
                d += ms[w * 264 + lane + 32 * j] * px[i * 264 + lane + 32 * j];
        }
        d = warp_sum(d);
        if (lane == 0) {
            if (w < ptr) {
                float m2 = m2s[w];
                float rm = (m2 == 0.f) ? 1.0f : rsqrtf(m2);
                sims[w] = d * rm * rxs[i];
            } else {
                sims[w] = -INFINITY;
            }
        }
        __syncthreads();
        if (w == 0) {
            float bv = sims[lane];
            int   bi = lane;
#pragma unroll
            for (int o = 16; o; o >>= 1) {
                float ov = __shfl_xor_sync(0xffffffffu, bv, o);
                int   oi = __shfl_xor_sync(0xffffffffu, bi, o);
                if (ov > bv || (ov == bv && oi < bi)) { bv = ov; bi = oi; }
            }
            int ema = (ptr > 0) && (bv >= threshold);
            int idx = ema ? bi : ptr;
            float ns2 = 0.f;
#pragma unroll
            for (int j = 0; j < 8; j++) {
                int c = lane + 32 * j;
                float xv = px[i * 264 + c];
                float nv = ema ? (ms[idx * 264 + c] * 0.9f + 0.1f * xv) : xv;
                ms[idx * 264 + c] = nv;
                ns2 += nv * nv;
            }
            ns2 = warp_sum(ns2);
            if (lane == 0) {
                m2s[idx] = ns2;
                if (!ema) s_ptr = ptr + 1;
            }
        }
        __syncthreads();
    }

    int ptr = s_ptr;
    for (int i = t; i < ptr * 256; i += 1024)
        g_mem[i] = ms[(i >> 8) * 264 + (i & 255)];
    if (t == 0) g_ptr = ptr;
}

// ---------------- proj GEMM: fp16 m16n8k16, BM=128, 512 threads ----------
__global__ __launch_bounds__(NTHREADS, 1)
void proj_mma(const float* __restrict__ feats,
              const float* __restrict__ preds,
              const float* __restrict__ W,
              const float* __restrict__ bias,
              float* __restrict__ out) {
    extern __shared__ char smem[];
    uint32_t* Au  = (uint32_t*)smem;               // A: [128][260] half2
    float* Bs     = (float*)(smem + A_BYTES);      // 4 stages [16][268] fp32
    float* pbuf   = (float*)(smem + PBUF_OFF);
    float* gacc   = (float*)(smem + GACC_OFF);

    int t = threadIdx.x, wid = t >> 5, lane = t & 31;
    int g = lane >> 2, tg = lane & 3;
    int b  = blockIdx.z;
    int m0 = blockIdx.y * BM;
    int n0 = blockIdx.x * BN;
    int warp_m = (wid >> 2) * 32;       // 0,32,64,96
    int warp_n = (wid & 3) * 64;        // 0,64,128,192
    bool do_g = (blockIdx.y == 0);

    const float* fb = feats + (size_t)b * CIN * HW + n0;
    uint32_t sB = smem_u32(Bs);

    if (do_g && t < 256) pbuf[t] = preds[(size_t)b * HW + n0 + t];

    // stage A slice (128 x 512) as packed half2
#pragma unroll
    for (int i = 0; i < 32; i++) {
        int c = t + i * NTHREADS;       // float4 id, 16384 total
        int row = c >> 7, col4 = (c & 127) * 4;
        float4 v = *(const float4*)(W + (size_t)(m0 + row) * CIN + col4);
        uint2 u;
        u.x = pack_h2(v.x, v.y);
        u.y = pack_h2(v.z, v.w);
        *(uint2*)(Au + row * A_STRIDE_U32 + (c & 127) * 2) = u;
    }

#pragma unroll
    for (int s = 0; s < NSTB - 1; s++) {
#pragma unroll
        for (int i = 0; i < 2; i++) {
            int c = t + i * NTHREADS;   // 16B chunk id, 1024 total
            int row = c >> 6, col16 = c & 63;
            CP_ASYNC16(sB + s * B_STAGE_BYTES + row * (B_STRIDE * 4) + col16 * 16,
                       fb + (size_t)(s * BK + row) * HW + col16 * 4);
        }
        CP_COMMIT();
    }

    float acc[2][8][4];
#pragma unroll
    for (int mt = 0; mt < 2; mt++)
#pragma unroll
        for (int nt = 0; nt < 8; nt++)
#pragma unroll
            for (int q = 0; q < 4; q++) acc[mt][nt][q] = 0.f;

    for (int kt = 0; kt < NKT; kt++) {
        CP_WAIT(2);
        __syncthreads();
        if (kt + NSTB - 1 < NKT) {
            int s = (kt + NSTB - 1) & (NSTB - 1);
#pragma unroll
            for (int i = 0; i < 2; i++) {
                int c = t + i * NTHREADS;
                int row = c >> 6, col16 = c & 63;
                CP_ASYNC16(sB + s * B_STAGE_BYTES + row * (B_STRIDE * 4) + col16 * 16,
                           fb + (size_t)((kt + NSTB - 1) * BK + row) * HW + col16 * 4);
            }
        }
        CP_COMMIT();

        const float* BsS = Bs + (kt & (NSTB - 1)) * (BK * B_STRIDE);

        if (do_g && t < 256) {
            int kk = t >> 4, seg = t & 15;
            float s = 0.f;
#pragma unroll
            for (int j = 0; j < 16; j++)
                s += BsS[kk * B_STRIDE + seg + 16 * j] * pbuf[seg + 16 * j];
#pragma unroll
            for (int o = 8; o; o >>= 1) s += __shfl_down_sync(0xffffffffu, s, o, 16);
            if (seg == 0) gacc[kt * 16 + kk] = s;
        }

        // fp16 m16n8k16 covers all 16 k per step
        uint32_t af[2][4];
#pragma unroll
        for (int mt = 0; mt < 2; mt++) {
            const uint32_t* ap = Au + (size_t)(warp_m + mt * 16 + g) * A_STRIDE_U32
                                 + kt * 8 + tg;
            af[mt][0] = ap[0];
            af[mt][1] = ap[8 * A_STRIDE_U32];
            af[mt][2] = ap[4];
            af[mt][3] = ap[8 * A_STRIDE_U32 + 4];
        }
        uint32_t bf[8][2];
        {
            const float* bk0 = BsS + (2 * tg) * B_STRIDE;       // k = 2tg
#pragma unroll
            for (int nt = 0; nt < 8; nt++) {
                int n = warp_n + nt * 8 + g;
                bf[nt][0] = pack_h2(bk0[n],                 bk0[B_STRIDE + n]);
                bf[nt][1] = pack_h2(bk0[8 * B_STRIDE + n],  bk0[9 * B_STRIDE + n]);
            }
        }
#pragma unroll
        for (int mt = 0; mt < 2; mt++)
#pragma unroll
            for (int nt = 0; nt < 8; nt++)
                MMA_F16(acc[mt][nt], af[mt], bf[nt]);
    }
    __syncthreads();

    if (do_g && t < 256) {
        g_part[blockIdx.x][b][t]       = gacc[t];
        g_part[blockIdx.x][b][t + 256] = gacc[t + 256];
    }

#pragma unroll
    for (int mt = 0; mt < 2; mt++) {
        int m = m0 + warp_m + mt * 16 + g;
        float bv0 = bias[m], bv1 = bias[m + 8];
        float* rowp = out + ((size_t)b * (2 * COUT) + m) * HW + n0 + warp_n + 2 * tg;
#pragma unroll
        for (int nt = 0; nt < 8; nt++) {
            *(float2*)(rowp + nt * 8)          = make_float2(acc[mt][nt][0] + bv0, acc[mt][nt][1] + bv0);
            *(float2*)(rowp + nt * 8 + 8 * HW) = make_float2(acc[mt][nt][2] + bv1, acc[mt][nt][3] + bv1);
        }
    }
}

// ---------------- attention v3 (unchanged) ----------------
__global__ __launch_bounds__(256, 2)
void attn_mma(float* __restrict__ out) {
    extern __shared__ char smc[];
    float* memS = (float*)(smc + AT_MEMS_OFF);
    float* lsm  = (float*)(smc + AT_LSM_OFF);
    float* stg  = (float*)(smc + AT_STG_OFF);

    int t = threadIdx.x, wid = t >> 5, lane = t & 31;
    int g = lane >> 2, tg = lane & 3;
    int b = blockIdx.y, l0 = blockIdx.x * 128;
    int ptr = g_ptr;

    for (int idx = t; idx < 32 * 256; idx += 256) {
        int p = idx >> 8, c = idx & 255;
        memS[p * MS_STRIDE + c] = (p < ptr) ? g_mem[idx] : 0.f;
    }

    const float* proj = out + (size_t)b * (2 * COUT) * HW;
    float* aug = out + (size_t)b * (2 * COUT) * HW + (size_t)COUT * HW + l0;
    uint32_t sStg = smem_u32(stg);

#define AT_LOAD(sidx, ktile) do {                                              \
    _Pragma("unroll")                                                          \
    for (int i = 0; i < 2; i++) {                                              \
        int c = t + i * 256;                                                   \
        int r = c >> 5, c16 = c & 31;                                          \
        CP_ASYNC16(sStg + (sidx) * AT_STAGE_BYTES + r * (LS_STRIDE * 4) + c16 * 16, \
                   proj + (size_t)((ktile) * 16 + r) * HW + l0 + c16 * 4);     \
    } } while (0)

    AT_LOAD(0, 0); CP_COMMIT();
    AT_LOAD(1, 1); CP_COMMIT();
    AT_LOAD(2, 2); CP_COMMIT();

    float accl[2][2][4];
#pragma unroll
    for (int mt = 0; mt < 2; mt++)
#pragma unroll
        for (int nt = 0; nt < 2; nt++)
#pragma unroll
            for (int q = 0; q < 4; q++) accl[mt][nt][q] = 0.f;
    int n0w = wid * 16;

    for (int kt = 0; kt < 16; kt++) {
        CP_WAIT(2);
        __syncthreads();
        if (kt + 3 < 16) AT_LOAD((kt + 3) & 3, kt + 3);
        CP_COMMIT();

        const float* BsS = stg + (kt & 3) * (16 * LS_STRIDE);
#pragma unroll
        for (int kk = 0; kk < 2; kk++) {
            int kc = kt * 16 + kk * 8;
            uint32_t af[2][4];
#pragma unroll
            for (int mt = 0; mt < 2; mt++) {
                const float* ap = memS + (mt * 16 + g) * MS_STRIDE + kc + tg;
                af[mt][0] = f2tf32(ap[0]);
                af[mt][1] = f2tf32(ap[8 * MS_STRIDE]);
                af[mt][2] = f2tf32(ap[4]);
                af[mt][3] = f2tf32(ap[8 * MS_STRIDE + 4]);
            }
            uint32_t bf[2][2];
#pragma unroll
            for (int nt = 0; nt < 2; nt++) {
                const float* bp = BsS + (kk * 8 + tg) * LS_STRIDE + n0w + nt * 8 + g;
                bf[nt][0] = f2tf32(bp[0]);
                bf[nt][1] = f2tf32(bp[4 * LS_STRIDE]);
            }
#pragma unroll
            for (int mt = 0; mt < 2; mt++)
#pragma unroll
                for (int nt = 0; nt < 2; nt++)
                    MMA_TF32(accl[mt][nt], af[mt], bf[nt]);
        }
    }
    __syncthreads();
#pragma unroll
    for (int mt = 0; mt < 2; mt++)
#pragma unroll
        for (int nt = 0; nt < 2; nt++) {
            int p = mt * 16 + g;
            int l = n0w + nt * 8 + 2 * tg;
            *(float2*)&lsm[p * LS_STRIDE + l]       = make_float2(accl[mt][nt][0], accl[mt][nt][1]);
            *(float2*)&lsm[(p + 8) * LS_STRIDE + l] = make_float2(accl[mt][nt][2], accl[mt][nt][3]);
        }
    __syncthreads();

    if (t < 128) {
        float mx = -INFINITY;
        for (int p = 0; p < ptr; p++) mx = fmaxf(mx, lsm[p * LS_STRIDE + t]);
        float ss = 0.f;
        for (int p = 0; p < ptr; p++) {
            float e = expf(lsm[p * LS_STRIDE + t] - mx);
            lsm[p * LS_STRIDE + t] = e;
            ss += e;
        }
        float inv = 1.0f / ss;
        for (int p = 0; p < ptr; p++) lsm[p * LS_STRIDE + t] *= inv;
        for (int p = ptr; p < 32; p++) lsm[p * LS_STRIDE + t] = 0.f;
    }
    __syncthreads();

    int m0w = wid * 32;
#pragma unroll
    for (int nh = 0; nh < 2; nh++) {
        float acca[2][8][4];
#pragma unroll
        for (int mt = 0; mt < 2; mt++)
#pragma unroll
            for (int nt = 0; nt < 8; nt++)
#pragma unroll
                for (int q = 0; q < 4; q++) acca[mt][nt][q] = 0.f;
#pragma unroll
        for (int ks = 0; ks < 4; ks++) {
            uint32_t af[2][4];
#pragma unroll
            for (int mt = 0; mt < 2; mt++) {
                const float* ap = memS + (ks * 8 + tg) * MS_STRIDE + m0w + mt * 16 + g;
                af[mt][0] = f2tf32(ap[0]);
                af[mt][1] = f2tf32(ap[8]);
                af[mt][2] = f2tf32(ap[4 * MS_STRIDE]);
                af[mt][3] = f2tf32(ap[4 * MS_STRIDE + 8]);
            }
            uint32_t bf[8][2];
#pragma unroll
            for (int nt = 0; nt < 8; nt++) {
                const float* bp = lsm + (ks * 8 + tg) * LS_STRIDE + nh * 64 + nt * 8 + g;
                bf[nt][0] = f2tf32(bp[0]);
                bf[nt][1] = f2tf32(bp[4 * LS_STRIDE]);
            }
#pragma unroll
            for (int mt = 0; mt < 2; mt++)
#pragma unroll
                for (int nt = 0; nt < 8; nt++)
                    MMA_TF32(acca[mt][nt], af[mt], bf[nt]);
        }
#pragma unroll
        for (int mt = 0; mt < 2; mt++) {
            int c = m0w + mt * 16 + g;
            float* r0 = aug + (size_t)c * HW + nh * 64 + 2 * tg;
            float* r1 = r0 + (size_t)8 * HW;
#pragma unroll
            for (int nt = 0; nt < 8; nt++) {
                *(float2*)(r0 + nt * 8) = make_float2(acca[mt][nt][0], acca[mt][nt][1]);
                *(float2*)(r1 + nt * 8) = make_float2(acca[mt][nt][2], acca[mt][nt][3]);
            }
        }
    }
#undef AT_LOAD
}

// ---------------- launch --------------------------------------------------
extern "C" void kernel_launch(void* const* d_in, const int* in_sizes, int n_in,
                              void* d_out, int out_size) {
    const float* feats = (const float*)d_in[0];
    const float* preds = (const float*)d_in[1];
    const float* W     = (const float*)d_in[2];
    const float* bias  = (const float*)d_in[3];
    const int*   epoch = (const int*)d_in[4];
    float* out = (float*)d_out;

    cudaFuncSetAttribute(proj_mma, cudaFuncAttributeMaxDynamicSharedMemorySize, SMEM_TOTAL);
    cudaFuncSetAttribute(attn_mma, cudaFuncAttributeMaxDynamicSharedMemorySize, AT_SMEM_TOTAL);

    predsum_kernel<<<BATCH, 256>>>(preds);
    proj_mma<<<dim3(HW / BN, COUT / BM, BATCH), NTHREADS, SMEM_TOTAL>>>(feats, preds, W, bias, out);
    pooled_kernel<<<BATCH, 256>>>(W, bias);
    memscan_kernel<<<1, 1024>>>(epoch);
    attn_mma<<<dim3(HW / 128, BATCH), 256, AT_SMEM_TOTAL>>>(out);
}